// round 9
// baseline (speedup 1.0000x reference)
#include <cuda_runtime.h>
#include <cuda_bf16.h>
#include <math.h>
#include <cstdint>

#define Bsz   2
#define Ssz   2048
#define INDIM 1024
#define EMB   1024
#define NH    16
#define HD    64
#define PADW  128

#define M1 (Bsz*Ssz)   /* 4096 */
#define N1 (3*EMB)     /* 3072 */

// ---------------------------------------------------------------------------
// Baseline-ISA PTX helpers (compute_103-legal)
// ---------------------------------------------------------------------------
__device__ __forceinline__ uint32_t smem_to_u32(const void* p) {
    uint32_t a;
    asm("{ .reg .u64 t; cvta.to.shared.u64 t, %1; cvt.u32.u64 %0, t; }" : "=r"(a) : "l"(p));
    return a;
}
#define CP_ASYNC16(saddr, gptr) \
    asm volatile("cp.async.cg.shared.global [%0], [%1], 16;" :: "r"(saddr), "l"(gptr))
#define CP_COMMIT() asm volatile("cp.async.commit_group;" ::: "memory")
#define CP_WAIT1()  asm volatile("cp.async.wait_group 1;" ::: "memory")
#define CP_WAIT0()  asm volatile("cp.async.wait_group 0;" ::: "memory")

__device__ __forceinline__ void ldm_x4(uint32_t* r, uint32_t addr) {
    asm volatile("ldmatrix.sync.aligned.m8n8.x4.shared.b16 {%0,%1,%2,%3}, [%4];"
        : "=r"(r[0]), "=r"(r[1]), "=r"(r[2]), "=r"(r[3]) : "r"(addr));
}
__device__ __forceinline__ void mma_bf16(float* d, const uint32_t* a, const uint32_t* b) {
    asm volatile("mma.sync.aligned.m16n8k16.row.col.f32.bf16.bf16.f32 "
        "{%0,%1,%2,%3}, {%4,%5,%6,%7}, {%8,%9}, {%0,%1,%2,%3};"
        : "+f"(d[0]), "+f"(d[1]), "+f"(d[2]), "+f"(d[3])
        : "r"(a[0]), "r"(a[1]), "r"(a[2]), "r"(a[3]), "r"(b[0]), "r"(b[1]));
}

// ---------------------------------------------------------------------------
// Scratch (static device globals)
// ---------------------------------------------------------------------------
__device__ __nv_bfloat16 g_xh[M1*INDIM],  g_xl[M1*INDIM];
__device__ __nv_bfloat16 g_wh[N1*INDIM],  g_wl[N1*INDIM];
__device__ __nv_bfloat16 g_woh[EMB*EMB],  g_wol[EMB*EMB];
__device__ __nv_bfloat16 g_qh[Bsz*NH*Ssz*HD], g_ql[Bsz*NH*Ssz*HD];
__device__ __nv_bfloat16 g_kh[Bsz*NH*Ssz*HD], g_kl[Bsz*NH*Ssz*HD];
__device__ __nv_bfloat16 g_vth[Bsz*NH*HD*Ssz], g_vtl[Bsz*NH*HD*Ssz];
__device__ __nv_bfloat16 g_avh[M1*EMB], g_avl[M1*EMB];

// ---------------------------------------------------------------------------
// fp32 -> bf16 hi/lo split kernels (inputs only)
// ---------------------------------------------------------------------------
__device__ __forceinline__ void split4_store(const float4 f,
                                             __nv_bfloat162* hi, __nv_bfloat162* lo, int i)
{
    __nv_bfloat16 h0 = __float2bfloat16(f.x), h1 = __float2bfloat16(f.y);
    __nv_bfloat16 h2 = __float2bfloat16(f.z), h3 = __float2bfloat16(f.w);
    hi[2*i]   = __halves2bfloat162(h0, h1);
    hi[2*i+1] = __halves2bfloat162(h2, h3);
    lo[2*i]   = __halves2bfloat162(__float2bfloat16(f.x - __bfloat162float(h0)),
                                   __float2bfloat16(f.y - __bfloat162float(h1)));
    lo[2*i+1] = __halves2bfloat162(__float2bfloat16(f.z - __bfloat162float(h2)),
                                   __float2bfloat16(f.w - __bfloat162float(h3)));
}
__global__ void split_x(const float4* __restrict__ in) {
    int i = blockIdx.x * blockDim.x + threadIdx.x;
    if (i < (M1*INDIM)/4)
        split4_store(in[i], (__nv_bfloat162*)g_xh, (__nv_bfloat162*)g_xl, i);
}
__global__ void split_w(const float4* __restrict__ in) {
    int i = blockIdx.x * blockDim.x + threadIdx.x;
    if (i < (N1*INDIM)/4)
        split4_store(in[i], (__nv_bfloat162*)g_wh, (__nv_bfloat162*)g_wl, i);
}
__global__ void split_wo(const float4* __restrict__ in) {
    int i = blockIdx.x * blockDim.x + threadIdx.x;
    if (i < (EMB*EMB)/4)
        split4_store(in[i], (__nv_bfloat162*)g_woh, (__nv_bfloat162*)g_wol, i);
}

// ---------------------------------------------------------------------------
// HMMA GEMM: CTA 128x256, BK=32, 8 warps, warp tile 64x64 (2m x 4n grid),
// double-buffered cp.async. Smem rows 40 bf16 (80 B), conflict-free.
// ---------------------------------------------------------------------------
#define A_TILE 10240            /* 128 rows * 80 B */
#define B_TILE 20480            /* 256 rows * 80 B */
#define BUF_SZ (2*A_TILE + 2*B_TILE)   /* 61440 */
#define GEMM_SMEM (2 * BUF_SZ)         /* 122880 */

__device__ __forceinline__ void load_tiles(
    const __nv_bfloat16* ah, const __nv_bfloat16* al,
    const __nv_bfloat16* bh, const __nv_bfloat16* bl,
    int m0, int n0, int k0, uint32_t sb, int buf, int t)
{
    uint32_t base = sb + buf * BUF_SZ;
    #pragma unroll
    for (int i = 0; i < 2; i++) {        // A: 128 rows
        int c  = t + i * 256;
        int r  = c >> 2;
        int kc = c & 3;
        size_t goff = (size_t)(m0 + r) * 1024 + k0 + kc * 8;
        uint32_t soff = (uint32_t)(r * 80 + kc * 16);
        CP_ASYNC16(base + soff,           ah + goff);
        CP_ASYNC16(base + A_TILE + soff,  al + goff);
    }
    #pragma unroll
    for (int i = 0; i < 4; i++) {        // B: 256 rows
        int c  = t + i * 256;
        int r  = c >> 2;
        int kc = c & 3;
        size_t goff = (size_t)(n0 + r) * 1024 + k0 + kc * 8;
        uint32_t soff = (uint32_t)(r * 80 + kc * 16);
        CP_ASYNC16(base + 2*A_TILE + soff,           bh + goff);
        CP_ASYNC16(base + 2*A_TILE + B_TILE + soff,  bl + goff);
    }
}

__device__ __forceinline__ void gemm_mainloop(
    const __nv_bfloat16* __restrict__ ah, const __nv_bfloat16* __restrict__ al,
    const __nv_bfloat16* __restrict__ bh, const __nv_bfloat16* __restrict__ bl,
    int m0, int n0, uint32_t sb, int t, float acc[4][8][4])
{
    const int lane = t & 31, wid = t >> 5;
    const int wm = (wid >> 2) * 64;      // 0 / 64
    const int wn = (wid & 3) * 64;       // 0 / 64 / 128 / 192

    #pragma unroll
    for (int a = 0; a < 4; a++)
        #pragma unroll
        for (int b = 0; b < 8; b++)
            #pragma unroll
            for (int e = 0; e < 4; e++)
                acc[a][b][e] = 0.f;

    load_tiles(ah, al, bh, bl, m0, n0, 0, sb, 0, t);
    CP_COMMIT();

    const int arow = wm + (lane & 15);
    const int akd  = (lane & 16) >> 1;
    const int nrow8 = (lane & 7) + ((lane & 16) >> 1);
    const int bkd  = (lane & 8);

    for (int ch = 0; ch < 32; ch++) {
        const int b = ch & 1;
        if (ch + 1 < 32) {
            load_tiles(ah, al, bh, bl, m0, n0, (ch + 1) * 32, sb, 1 - b, t);
            CP_COMMIT();
            CP_WAIT1();
        } else {
            CP_WAIT0();
        }
        __syncthreads();

        const uint32_t base = sb + b * BUF_SZ;
        #pragma unroll
        for (int ks = 0; ks < 2; ks++) {
            const int kk = ks * 16;
            uint32_t ahf[4][4], alf[4][4], bhf[4][4], blf[4][4];
            #pragma unroll
            for (int mt = 0; mt < 4; mt++) {
                uint32_t off = (uint32_t)((arow + mt * 16) * 80 + (kk + akd) * 2);
                ldm_x4(ahf[mt], base + off);
                ldm_x4(alf[mt], base + A_TILE + off);
            }
            #pragma unroll
            for (int g = 0; g < 4; g++) {
                uint32_t off = (uint32_t)((wn + nrow8 + g * 16) * 80 + (kk + bkd) * 2);
                ldm_x4(bhf[g], base + 2*A_TILE + off);
                ldm_x4(blf[g], base + 2*A_TILE + B_TILE + off);
            }
            #pragma unroll
            for (int mt = 0; mt < 4; mt++)
                #pragma unroll
                for (int nt = 0; nt < 8; nt++) {
                    const uint32_t* b2h = &bhf[nt >> 1][(nt & 1) * 2];
                    const uint32_t* b2l = &blf[nt >> 1][(nt & 1) * 2];
                    mma_bf16(acc[mt][nt], ahf[mt], b2h);
                    mma_bf16(acc[mt][nt], ahf[mt], b2l);
                    mma_bf16(acc[mt][nt], alf[mt], b2h);
                }
        }
        __syncthreads();
    }
}

// QKV projection: bias + padding mask + bf16 hi/lo split epilogue,
// scatter q,k [b,h,s,d] and v transposed [b,h,d,s].
__global__ __launch_bounds__(256, 1) void qkv_mma(
    const float* __restrict__ bias, const int* __restrict__ pm)
{
    extern __shared__ __align__(16) char smem[];
    const uint32_t sb = smem_to_u32(smem);
    const int t = threadIdx.x, lane = t & 31, wid = t >> 5;
    const int wm = (wid >> 2) * 64, wn = (wid & 3) * 64;
    const int n0 = blockIdx.x * 256, m0 = blockIdx.y * 128;

    float acc[4][8][4];
    gemm_mainloop(g_xh, g_xl, g_wh, g_wl, m0, n0, sb, t, acc);

    const int lr = lane >> 2, lc = (lane & 3) * 2;
    #pragma unroll
    for (int mt = 0; mt < 4; mt++) {
        #pragma unroll
        for (int half = 0; half < 2; half++) {
            const int m = m0 + wm + mt * 16 + lr + half * 8;
            const int msk = pm[m];
            const int bb = m >> 11, s = m & 2047;
            #pragma unroll
            for (int nt = 0; nt < 8; nt++) {
                #pragma unroll
                for (int e = 0; e < 2; e++) {
                    const int n = n0 + wn + nt * 8 + lc + e;
                    float val = msk ? 0.0f : (acc[mt][nt][half * 2 + e] + bias[n]);
                    __nv_bfloat16 vh = __float2bfloat16(val);
                    __nv_bfloat16 vl = __float2bfloat16(val - __bfloat162float(vh));
                    int h  = n / 192;
                    int cc = n - h * 192;
                    if (cc < HD) {
                        int idx = ((bb * NH + h) * Ssz + s) * HD + cc;
                        g_qh[idx] = vh; g_ql[idx] = vl;
                    } else if (cc < 2*HD) {
                        int idx = ((bb * NH + h) * Ssz + s) * HD + cc - HD;
                        g_kh[idx] = vh; g_kl[idx] = vl;
                    } else {
                        int idx = ((bb * NH + h) * HD + cc - 2*HD) * Ssz + s;
                        g_vth[idx] = vh; g_vtl[idx] = vl;
                    }
                }
            }
        }
    }
}

// Output projection: out = attn_vals @ Wo^T + bo
__global__ __launch_bounds__(256, 1) void out_mma(
    const float* __restrict__ bias, float* __restrict__ C)
{
    extern __shared__ __align__(16) char smem[];
    const uint32_t sb = smem_to_u32(smem);
    const int t = threadIdx.x, lane = t & 31, wid = t >> 5;
    const int wm = (wid >> 2) * 64, wn = (wid & 3) * 64;
    const int n0 = blockIdx.x * 256, m0 = blockIdx.y * 128;

    float acc[4][8][4];
    gemm_mainloop(g_avh, g_avl, g_woh, g_wol, m0, n0, sb, t, acc);

    const int lr = lane >> 2, lc = (lane & 3) * 2;
    #pragma unroll
    for (int mt = 0; mt < 4; mt++) {
        #pragma unroll
        for (int half = 0; half < 2; half++) {
            const int m = m0 + wm + mt * 16 + lr + half * 8;
            #pragma unroll
            for (int nt = 0; nt < 8; nt++) {
                const int n = n0 + wn + nt * 8 + lc;
                float2 o;
                o.x = acc[mt][nt][half * 2 + 0] + bias[n];
                o.y = acc[mt][nt][half * 2 + 1] + bias[n + 1];
                *reinterpret_cast<float2*>(C + (size_t)m * EMB + n) = o;
            }
        }
    }
}

// ---------------------------------------------------------------------------
// Tensor-core banded attention (validated round 8, unchanged).
// ---------------------------------------------------------------------------
#define SW   328
#define ARS  144
#define OFF_QH  0
#define OFF_QL  9216
#define OFF_KH  18432
#define OFF_KL  27648
#define OFF_PH  36864
#define OFF_PL  46080
#define OFF_SC  55296
#define OFF_INV 139264
#define ATTN_SMEM 139520

__global__ __launch_bounds__(256) void attn_kernel()
{
    extern __shared__ __align__(16) char smem[];
    const uint32_t sbase = smem_to_u32(smem);
    float* sc    = (float*)(smem + OFF_SC);
    float* inv_s = (float*)(smem + OFF_INV);

    const int t = threadIdx.x, lane = t & 31, w = t >> 5;
    const int b  = blockIdx.y >> 4, h = blockIdx.y & 15;
    const int qs = blockIdx.x * 64;
    const int kb = qs - PADW;

    const size_t qkbase = (size_t)(b * NH + h) * Ssz * HD;
    const size_t vbase  = (size_t)(b * NH + h) * HD * Ssz;

    const int wm4 = (w >> 1) << 4;
    const int wn  = (w & 1) << 5;
    const int arow = wm4 + (lane & 15);
    const int akd  = (lane & 16) >> 1;
    const int nrow8 = (lane & 7) + ((lane & 16) >> 1);
    const int bkd  = (lane & 8);
    const int lr = lane >> 2, lc = (lane & 3) * 2;

    {
        #pragma unroll
        for (int i = 0; i < 2; i++) {
            int u   = t + i * 256;
            int row = u >> 3;
            int c8  = (u & 7) * 8;
            uint32_t soff = (uint32_t)(row * ARS + c8 * 2);
            *reinterpret_cast<uint4*>(smem + OFF_QH + soff) =
                *reinterpret_cast<const uint4*>(g_qh + qkbase + (size_t)(qs + row) * HD + c8);
            *reinterpret_cast<uint4*>(smem + OFF_QL + soff) =
                *reinterpret_cast<const uint4*>(g_ql + qkbase + (size_t)(qs + row) * HD + c8);
        }
    }

    for (int ch = 0; ch < 5; ch++) {
        __syncthreads();
        #pragma unroll
        for (int i = 0; i < 2; i++) {
            int u   = t + i * 256;
            int row = u >> 3;
            int c8  = (u & 7) * 8;
            int j   = kb + ch * 64 + row;
            uint32_t soff = (uint32_t)(row * ARS + c8 * 2);
            uint4 vh = make_uint4(0,0,0,0), vl = make_uint4(0,0,0,0);
            if (j >= 0 && j < Ssz) {
                vh = *reinterpret_cast<const uint4*>(g_kh + qkbase + (size_t)j * HD + c8);
                vl = *reinterpret_cast<const uint4*>(g_kl + qkbase + (size_t)j * HD + c8);
            }
            *reinterpret_cast<uint4*>(smem + OFF_KH + soff) = vh;
            *reinterpret_cast<uint4*>(smem + OFF_KL + soff) = vl;
        }
        __syncthreads();

        float acc[4][4];
        #pragma unroll
        for (int nt = 0; nt < 4; nt++)
            #pragma unroll
            for (int e = 0; e < 4; e++) acc[nt][e] = 0.f;

        #pragma unroll
        for (int ks = 0; ks < 4; ks++) {
            const int kk = ks * 16;
            uint32_t qh4[4], ql4[4], kh4[2][4], kl4[2][4];
            uint32_t aoff = (uint32_t)(arow * ARS + (kk + akd) * 2);
            ldm_x4(qh4, sbase + OFF_QH + aoff);
            ldm_x4(ql4, sbase + OFF_QL + aoff);
            #pragma unroll
            for (int g = 0; g < 2; g++) {
                uint32_t boff = (uint32_t)((wn + nrow8 + g * 16) * ARS + (kk + bkd) * 2);
                ldm_x4(kh4[g], sbase + OFF_KH + boff);
                ldm_x4(kl4[g], sbase + OFF_KL + boff);
            }
            #pragma unroll
            for (int nt = 0; nt < 4; nt++) {
                const uint32_t* b2h = &kh4[nt >> 1][(nt & 1) * 2];
                const uint32_t* b2l = &kl4[nt >> 1][(nt & 1) * 2];
                mma_bf16(acc[nt], qh4, b2h);
                mma_bf16(acc[nt], qh4, b2l);
                mma_bf16(acc[nt], ql4, b2h);
            }
        }
        #pragma unroll
        for (int nt = 0; nt < 4; nt++) {
            #pragma unroll
            for (int half = 0; half < 2; half++) {
                int r = wm4 + lr + half * 8;
                int c = ch * 64 + wn + nt * 8 + lc;
                sc[r * SW + c]     = acc[nt][half * 2 + 0];
                sc[r * SW + c + 1] = acc[nt][half * 2 + 1];
            }
        }
    }
    __syncthreads();

    {
        const int r = t >> 2, g = t & 3;
        const float scale = 0.125f;
        float mx = -1e30f;
        for (int c = g; c < 320; c += 4) {
            int j = kb + c;
            if (j >= 0 && j < Ssz && c >= r && c <= r + 256)
                mx = fmaxf(mx, sc[r * SW + c]);
        }
        mx = fmaxf(mx, __shfl_xor_sync(0xffffffffu, mx, 1));
        mx = fmaxf(mx, __shfl_xor_sync(0xffffffffu, mx, 2));
        float mxs = mx * scale;
        float sum = 0.f;
        for (int c = g; c < 320; c += 4) {
            int j = kb + c;
            float e = 0.f;
            if (j >= 0 && j < Ssz && c >= r && c <= r + 256)
                e = __expf(sc[r * SW + c] * scale - mxs);
            sc[r * SW + c] = e;
            sum += e;
        }
        sum += __shfl_xor_sync(0xffffffffu, sum, 1);
        sum += __shfl_xor_sync(0xffffffffu, sum, 2);
        if (g == 0) inv_s[r] = 1.0f / sum;
    }

    float acc2[4][4];
    #pragma unroll
    for (int nt = 0; nt < 4; nt++)
        #pragma unroll
        for (int e = 0; e < 4; e++) acc2[nt][e] = 0.f;

    for (int ch = 0; ch < 5; ch++) {
        __syncthreads();
        #pragma unroll
        for (int i = 0; i < 2; i++) {
            int u   = t + i * 256;
            int row = u >> 3;
            int c8  = (u & 7) * 8;
            int j0  = kb + ch * 64 + c8;
            uint32_t soff = (uint32_t)(row * ARS + c8 * 2);
            uint4 vh = make_uint4(0,0,0,0), vl = make_uint4(0,0,0,0);
            if (j0 >= 0 && j0 < Ssz) {
                vh = *reinterpret_cast<const uint4*>(g_vth + vbase + (size_t)row * Ssz + j0);
                vl = *reinterpret_cast<const uint4*>(g_vtl + vbase + (size_t)row * Ssz + j0);
            }
            *reinterpret_cast<uint4*>(smem + OFF_KH + soff) = vh;
            *reinterpret_cast<uint4*>(smem + OFF_KL + soff) = vl;
        }
        #pragma unroll
        for (int i = 0; i < 8; i++) {
            int p  = t + i * 256;
            int r  = p >> 5;
            int c2 = (p & 31) * 2;
            float e0 = sc[r * SW + ch * 64 + c2];
            float e1 = sc[r * SW + ch * 64 + c2 + 1];
            __nv_bfloat16 h0 = __float2bfloat16(e0), h1 = __float2bfloat16(e1);
            __nv_bfloat162 ph = __halves2bfloat162(h0, h1);
            __nv_bfloat162 pl = __halves2bfloat162(
                __float2bfloat16(e0 - __bfloat162float(h0)),
                __float2bfloat16(e1 - __bfloat162float(h1)));
            *reinterpret_cast<__nv_bfloat162*>(smem + OFF_PH + r * ARS + c2 * 2) = ph;
            *reinterpret_cast<__nv_bfloat162*>(smem + OFF_PL + r * ARS + c2 * 2) = pl;
        }
        __syncthreads();

        #pragma unroll
        for (int ks = 0; ks < 4; ks++) {
            const int kk = ks * 16;
            uint32_t ph4[4], pl4[4], vh4[2][4], vl4[2][4];
            uint32_t aoff = (uint32_t)(arow * ARS + (kk + akd) * 2);
            ldm_x4(ph4, sbase + OFF_PH + aoff);
            ldm_x4(pl4, sbase + OFF_PL + aoff);
            #pragma unroll
            for (int g = 0; g < 2; g++) {
                uint32_t boff = (uint32_t)((wn + nrow8 + g * 16) * ARS + (kk + bkd) * 2);
                ldm_x4(vh4[g], sbase + OFF_KH + boff);
                ldm_x4(vl4[g], sbase + OFF_KL + boff);
            }
            #pragma unroll
            for (int nt = 0; nt < 4; nt++) {
                const uint32_t* b2h = &vh4[nt >> 1][(nt & 1) * 2];
                const uint32_t* b2l = &vl4[nt >> 1][(nt & 1) * 2];
                mma_bf16(acc2[nt], ph4, b2h);
                mma_bf16(acc2[nt], ph4, b2l);
                mma_bf16(acc2[nt], pl4, b2h);
            }
        }
    }
    __syncthreads();

    #pragma unroll
    for (int half = 0; half < 2; half++) {
        const int r  = wm4 + lr + half * 8;
        const float is = inv_s[r];
        const size_t rowbase = (size_t)(b * Ssz + qs + r) * EMB + h * HD;
        #pragma unroll
        for (int nt = 0; nt < 4; nt++) {
            #pragma unroll
            for (int e = 0; e < 2; e++) {
                const int d = wn + nt * 8 + lc + e;
                float val = acc2[nt][half * 2 + e] * is;
                __nv_bfloat16 vh = __float2bfloat16(val);
                g_avh[rowbase + d] = vh;
                g_avl[rowbase + d] = __float2bfloat16(val - __bfloat162float(vh));
            }
        }
    }
}

// ---------------------------------------------------------------------------
extern "C" void kernel_launch(void* const* d_in, const int* in_sizes, int n_in,
                              void* d_out, int out_size)
{
    const float* x    = (const float*)d_in[0];
    const int*   pm   = (const int*)  d_in[1];
    const float* Wqkv = (const float*)d_in[2];
    const float* bqkv = (const float*)d_in[3];
    const float* Wo   = (const float*)d_in[4];
    const float* bo   = (const float*)d_in[5];
    float* out = (float*)d_out;

    cudaFuncSetAttribute(attn_kernel,
                         cudaFuncAttributeMaxDynamicSharedMemorySize, ATTN_SMEM);
    cudaFuncSetAttribute(qkv_mma,
                         cudaFuncAttributeMaxDynamicSharedMemorySize, GEMM_SMEM);
    cudaFuncSetAttribute(out_mma,
                         cudaFuncAttributeMaxDynamicSharedMemorySize, GEMM_SMEM);

    split_x <<<(M1*INDIM/4 + 255)/256, 256>>>((const float4*)x);
    split_w <<<(N1*INDIM/4 + 255)/256, 256>>>((const float4*)Wqkv);
    split_wo<<<(EMB*EMB/4  + 255)/256, 256>>>((const float4*)Wo);

    qkv_mma<<<dim3(N1/256, M1/128), 256, GEMM_SMEM>>>(bqkv, pm);

    attn_kernel<<<dim3(Ssz/64, Bsz*NH), 256, ATTN_SMEM>>>();

    out_mma<<<dim3(EMB/256, M1/128), 256, GEMM_SMEM>>>(bo, out);
}

// round 10
// speedup vs baseline: 1.2045x; 1.2045x over previous
#include <cuda_runtime.h>
#include <cuda_bf16.h>
#include <math.h>
#include <cstdint>

#define Bsz   2
#define Ssz   2048
#define INDIM 1024
#define EMB   1024
#define NH    16
#define HD    64
#define PADW  128

#define M1 (Bsz*Ssz)   /* 4096 */
#define N1 (3*EMB)     /* 3072 */

// ---------------------------------------------------------------------------
// Baseline-ISA PTX helpers (compute_103-legal)
// ---------------------------------------------------------------------------
__device__ __forceinline__ uint32_t smem_to_u32(const void* p) {
    uint32_t a;
    asm("{ .reg .u64 t; cvta.to.shared.u64 t, %1; cvt.u32.u64 %0, t; }" : "=r"(a) : "l"(p));
    return a;
}
#define CP_ASYNC16(saddr, gptr) \
    asm volatile("cp.async.cg.shared.global [%0], [%1], 16;" :: "r"(saddr), "l"(gptr))
#define CP_COMMIT() asm volatile("cp.async.commit_group;" ::: "memory")
#define CP_WAIT1()  asm volatile("cp.async.wait_group 1;" ::: "memory")
#define CP_WAIT0()  asm volatile("cp.async.wait_group 0;" ::: "memory")

__device__ __forceinline__ void ldm_x4(uint32_t* r, uint32_t addr) {
    asm volatile("ldmatrix.sync.aligned.m8n8.x4.shared.b16 {%0,%1,%2,%3}, [%4];"
        : "=r"(r[0]), "=r"(r[1]), "=r"(r[2]), "=r"(r[3]) : "r"(addr));
}
__device__ __forceinline__ void mma_bf16(float* d, const uint32_t* a, const uint32_t* b) {
    asm volatile("mma.sync.aligned.m16n8k16.row.col.f32.bf16.bf16.f32 "
        "{%0,%1,%2,%3}, {%4,%5,%6,%7}, {%8,%9}, {%0,%1,%2,%3};"
        : "+f"(d[0]), "+f"(d[1]), "+f"(d[2]), "+f"(d[3])
        : "r"(a[0]), "r"(a[1]), "r"(a[2]), "r"(a[3]), "r"(b[0]), "r"(b[1]));
}

// ---------------------------------------------------------------------------
// Scratch (static device globals)
// ---------------------------------------------------------------------------
__device__ __nv_bfloat16 g_xh[M1*INDIM],  g_xl[M1*INDIM];
__device__ __nv_bfloat16 g_wh[N1*INDIM],  g_wl[N1*INDIM];
__device__ __nv_bfloat16 g_woh[EMB*EMB],  g_wol[EMB*EMB];
__device__ __nv_bfloat16 g_qh[Bsz*NH*Ssz*HD], g_ql[Bsz*NH*Ssz*HD];
__device__ __nv_bfloat16 g_kh[Bsz*NH*Ssz*HD], g_kl[Bsz*NH*Ssz*HD];
__device__ __nv_bfloat16 g_vth[Bsz*NH*HD*Ssz], g_vtl[Bsz*NH*HD*Ssz];
__device__ __nv_bfloat16 g_avh[M1*EMB], g_avl[M1*EMB];

// ---------------------------------------------------------------------------
// fp32 -> bf16 hi/lo split kernels (inputs only)
// ---------------------------------------------------------------------------
__device__ __forceinline__ void split4_store(const float4 f,
                                             __nv_bfloat162* hi, __nv_bfloat162* lo, int i)
{
    __nv_bfloat16 h0 = __float2bfloat16(f.x), h1 = __float2bfloat16(f.y);
    __nv_bfloat16 h2 = __float2bfloat16(f.z), h3 = __float2bfloat16(f.w);
    hi[2*i]   = __halves2bfloat162(h0, h1);
    hi[2*i+1] = __halves2bfloat162(h2, h3);
    lo[2*i]   = __halves2bfloat162(__float2bfloat16(f.x - __bfloat162float(h0)),
                                   __float2bfloat16(f.y - __bfloat162float(h1)));
    lo[2*i+1] = __halves2bfloat162(__float2bfloat16(f.z - __bfloat162float(h2)),
                                   __float2bfloat16(f.w - __bfloat162float(h3)));
}
__global__ void split_x(const float4* __restrict__ in) {
    int i = blockIdx.x * blockDim.x + threadIdx.x;
    if (i < (M1*INDIM)/4)
        split4_store(in[i], (__nv_bfloat162*)g_xh, (__nv_bfloat162*)g_xl, i);
}
__global__ void split_w(const float4* __restrict__ in) {
    int i = blockIdx.x * blockDim.x + threadIdx.x;
    if (i < (N1*INDIM)/4)
        split4_store(in[i], (__nv_bfloat162*)g_wh, (__nv_bfloat162*)g_wl, i);
}
__global__ void split_wo(const float4* __restrict__ in) {
    int i = blockIdx.x * blockDim.x + threadIdx.x;
    if (i < (EMB*EMB)/4)
        split4_store(in[i], (__nv_bfloat162*)g_woh, (__nv_bfloat162*)g_wol, i);
}

// ---------------------------------------------------------------------------
// HMMA GEMM (round-8 validated config): CTA 128x128, BK=32, 8 warps,
// warp tile 64x32, double-buffered cp.async, 80 B smem rows. 2 CTAs/SM.
// ---------------------------------------------------------------------------
#define TILE_B 10240
#define GEMM_SMEM (8 * TILE_B)

__device__ __forceinline__ void load4_async(
    const __nv_bfloat16* ah, const __nv_bfloat16* al,
    const __nv_bfloat16* bh, const __nv_bfloat16* bl,
    int m0, int n0, int k0, uint32_t sb, int buf, int t)
{
    uint32_t base = sb + buf * 4 * TILE_B;
    #pragma unroll
    for (int i = 0; i < 2; i++) {
        int c  = t + i * 256;
        int r  = c >> 2;
        int kc = c & 3;
        size_t goffA = (size_t)(m0 + r) * 1024 + k0 + kc * 8;
        size_t goffB = (size_t)(n0 + r) * 1024 + k0 + kc * 8;
        uint32_t soff = (uint32_t)(r * 80 + kc * 16);
        CP_ASYNC16(base + 0*TILE_B + soff, ah + goffA);
        CP_ASYNC16(base + 1*TILE_B + soff, al + goffA);
        CP_ASYNC16(base + 2*TILE_B + soff, bh + goffB);
        CP_ASYNC16(base + 3*TILE_B + soff, bl + goffB);
    }
}

__device__ __forceinline__ void gemm_mainloop(
    const __nv_bfloat16* __restrict__ ah, const __nv_bfloat16* __restrict__ al,
    const __nv_bfloat16* __restrict__ bh, const __nv_bfloat16* __restrict__ bl,
    int m0, int n0, uint32_t sb, int t, float acc[4][4][4])
{
    const int lane = t & 31, wid = t >> 5;
    const int wm = (wid >> 2) * 64, wn = (wid & 3) * 32;

    #pragma unroll
    for (int a = 0; a < 4; a++)
        #pragma unroll
        for (int b = 0; b < 4; b++)
            #pragma unroll
            for (int e = 0; e < 4; e++)
                acc[a][b][e] = 0.f;

    load4_async(ah, al, bh, bl, m0, n0, 0, sb, 0, t);
    CP_COMMIT();

    const int arow = wm + (lane & 15);
    const int akd  = (lane & 16) >> 1;
    const int nrow = wn + (lane & 7) + ((lane & 16) >> 1);
    const int bkd  = (lane & 8);

    for (int ch = 0; ch < 32; ch++) {
        const int b = ch & 1;
        if (ch + 1 < 32) {
            load4_async(ah, al, bh, bl, m0, n0, (ch + 1) * 32, sb, 1 - b, t);
            CP_COMMIT();
            CP_WAIT1();
        } else {
            CP_WAIT0();
        }
        __syncthreads();

        const uint32_t base = sb + b * 4 * TILE_B;
        #pragma unroll
        for (int ks = 0; ks < 2; ks++) {
            const int kk = ks * 16;
            uint32_t ahf[4][4], alf[4][4], bhf[2][4], blf[2][4];
            #pragma unroll
            for (int mt = 0; mt < 4; mt++) {
                uint32_t off = (uint32_t)((arow + mt * 16) * 80 + (kk + akd) * 2);
                ldm_x4(ahf[mt], base + 0*TILE_B + off);
                ldm_x4(alf[mt], base + 1*TILE_B + off);
            }
            #pragma unroll
            for (int g = 0; g < 2; g++) {
                uint32_t off = (uint32_t)((nrow + g * 16) * 80 + (kk + bkd) * 2);
                ldm_x4(bhf[g], base + 2*TILE_B + off);
                ldm_x4(blf[g], base + 3*TILE_B + off);
            }
            #pragma unroll
            for (int mt = 0; mt < 4; mt++)
                #pragma unroll
                for (int nt = 0; nt < 4; nt++) {
                    const uint32_t* b2h = &bhf[nt >> 1][(nt & 1) * 2];
                    const uint32_t* b2l = &blf[nt >> 1][(nt & 1) * 2];
                    mma_bf16(acc[mt][nt], ahf[mt], b2h);
                    mma_bf16(acc[mt][nt], ahf[mt], b2l);
                    mma_bf16(acc[mt][nt], alf[mt], b2h);
                }
        }
        __syncthreads();
    }
}

// QKV projection: bias + padding mask + bf16 hi/lo split epilogue,
// scatter q,k [b,h,s,d] and v transposed [b,h,d,s].
__global__ __launch_bounds__(256) void qkv_mma(
    const float* __restrict__ bias, const int* __restrict__ pm)
{
    extern __shared__ __align__(16) char smem[];
    const uint32_t sb = smem_to_u32(smem);
    const int t = threadIdx.x, lane = t & 31, wid = t >> 5;
    const int wm = (wid >> 2) * 64, wn = (wid & 3) * 32;
    const int n0 = blockIdx.x * 128, m0 = blockIdx.y * 128;

    float acc[4][4][4];
    gemm_mainloop(g_xh, g_xl, g_wh, g_wl, m0, n0, sb, t, acc);

    const int lr = lane >> 2, lc = (lane & 3) * 2;
    #pragma unroll
    for (int mt = 0; mt < 4; mt++) {
        #pragma unroll
        for (int half = 0; half < 2; half++) {
            const int m = m0 + wm + mt * 16 + lr + half * 8;
            const int msk = pm[m];
            const int bb = m >> 11, s = m & 2047;
            #pragma unroll
            for (int nt = 0; nt < 4; nt++) {
                #pragma unroll
                for (int e = 0; e < 2; e++) {
                    const int n = n0 + wn + nt * 8 + lc + e;
                    float val = msk ? 0.0f : (acc[mt][nt][half * 2 + e] + bias[n]);
                    __nv_bfloat16 vh = __float2bfloat16(val);
                    __nv_bfloat16 vl = __float2bfloat16(val - __bfloat162float(vh));
                    int h  = n / 192;
                    int cc = n - h * 192;
                    if (cc < HD) {
                        int idx = ((bb * NH + h) * Ssz + s) * HD + cc;
                        g_qh[idx] = vh; g_ql[idx] = vl;
                    } else if (cc < 2*HD) {
                        int idx = ((bb * NH + h) * Ssz + s) * HD + cc - HD;
                        g_kh[idx] = vh; g_kl[idx] = vl;
                    } else {
                        int idx = ((bb * NH + h) * HD + cc - 2*HD) * Ssz + s;
                        g_vth[idx] = vh; g_vtl[idx] = vl;
                    }
                }
            }
        }
    }
}

// Output projection: out = attn_vals @ Wo^T + bo
__global__ __launch_bounds__(256) void out_mma(
    const float* __restrict__ bias, float* __restrict__ C)
{
    extern __shared__ __align__(16) char smem[];
    const uint32_t sb = smem_to_u32(smem);
    const int t = threadIdx.x, lane = t & 31, wid = t >> 5;
    const int wm = (wid >> 2) * 64, wn = (wid & 3) * 32;
    const int n0 = blockIdx.x * 128, m0 = blockIdx.y * 128;

    float acc[4][4][4];
    gemm_mainloop(g_avh, g_avl, g_woh, g_wol, m0, n0, sb, t, acc);

    const int lr = lane >> 2, lc = (lane & 3) * 2;
    #pragma unroll
    for (int mt = 0; mt < 4; mt++) {
        #pragma unroll
        for (int half = 0; half < 2; half++) {
            const int m = m0 + wm + mt * 16 + lr + half * 8;
            #pragma unroll
            for (int nt = 0; nt < 4; nt++) {
                const int n = n0 + wn + nt * 8 + lc;
                float2 o;
                o.x = acc[mt][nt][half * 2 + 0] + bias[n];
                o.y = acc[mt][nt][half * 2 + 1] + bias[n + 1];
                *reinterpret_cast<float2*>(C + (size_t)m * EMB + n) = o;
            }
        }
    }
}

// ---------------------------------------------------------------------------
// Banded attention with ONLINE softmax (no score buffer): 75 KB smem,
// 2 CTAs/SM. One block per (b,h,64-query tile), 256 threads.
// Masked scores are set to -1e30 so exp underflows to exactly 0 (same
// semantics as the reference's -9e15 fill). Early all-masked chunks produce
// sum garbage that is annihilated by the alpha=0 rescale; their PV
// contribution is 0 because invalid V columns are zeroed.
// ---------------------------------------------------------------------------
#define ARS  144
#define OFF_QH  0
#define OFF_QL  9216
#define OFF_KH  18432
#define OFF_KL  27648
#define OFF_VH  36864
#define OFF_VL  46080
#define OFF_PH  55296
#define OFF_PL  64512
#define OFF_MR  73728                 /* m_run[64]   */
#define OFF_SR  (OFF_MR + 256)        /* sum_run[64] */
#define OFF_ALP (OFF_MR + 512)        /* alpha[64]   */
#define OFF_ST  (OFF_MR + 768)        /* stats[64][2]*/
#define ATTN_SMEM (OFF_MR + 768 + 512)   /* 75008 */

__global__ __launch_bounds__(256, 2) void attn_kernel()
{
    extern __shared__ __align__(16) char smem[];
    const uint32_t sbase = smem_to_u32(smem);
    float* m_run = (float*)(smem + OFF_MR);
    float* s_run = (float*)(smem + OFF_SR);
    float* alphv = (float*)(smem + OFF_ALP);
    float* stats = (float*)(smem + OFF_ST);

    const int t = threadIdx.x, lane = t & 31, w = t >> 5;
    const int b  = blockIdx.y >> 4, h = blockIdx.y & 15;
    const int qs = blockIdx.x * 64;
    const int kb = qs - PADW;

    const size_t qkbase = (size_t)(b * NH + h) * Ssz * HD;
    const size_t vbase  = (size_t)(b * NH + h) * HD * Ssz;

    const int wm4 = (w >> 1) << 4;        // m-group base (0/16/32/48)
    const int wnI = w & 1;                // n-group index
    const int wn  = wnI << 5;             // n-group base (0/32)
    const int arow = wm4 + (lane & 15);
    const int akd  = (lane & 16) >> 1;
    const int nrow8 = (lane & 7) + ((lane & 16) >> 1);
    const int bkd  = (lane & 8);
    const int lr = lane >> 2, lc = (lane & 3) * 2;
    const int r0 = wm4 + lr;              // this thread's rows: r0, r0+8
    const float scale = 0.125f;

    // init running stats + load Q tile
    if (t < 64) { m_run[t] = -1e30f; s_run[t] = 0.f; }
    #pragma unroll
    for (int i = 0; i < 2; i++) {
        int u = t + i * 256;
        int row = u >> 3;
        int c8  = (u & 7) * 8;
        uint32_t soff = (uint32_t)(row * ARS + c8 * 2);
        *reinterpret_cast<uint4*>(smem + OFF_QH + soff) =
            *reinterpret_cast<const uint4*>(g_qh + qkbase + (size_t)(qs + row) * HD + c8);
        *reinterpret_cast<uint4*>(smem + OFF_QL + soff) =
            *reinterpret_cast<const uint4*>(g_ql + qkbase + (size_t)(qs + row) * HD + c8);
    }

    float acc2[4][4];
    #pragma unroll
    for (int nt = 0; nt < 4; nt++)
        #pragma unroll
        for (int e = 0; e < 4; e++) acc2[nt][e] = 0.f;

    for (int ch = 0; ch < 5; ch++) {
        __syncthreads();   // prev MMA/stat reads done; Q visible (1st iter)
        // ---- load K chunk [key 64][d 64] and V^T chunk [d 64][key 64] ----
        #pragma unroll
        for (int i = 0; i < 2; i++) {
            int u   = t + i * 256;
            int row = u >> 3;
            int c8  = (u & 7) * 8;
            uint32_t soff = (uint32_t)(row * ARS + c8 * 2);
            int j = kb + ch * 64 + row;
            uint4 kh = make_uint4(0,0,0,0), kl = make_uint4(0,0,0,0);
            if (j >= 0 && j < Ssz) {
                kh = *reinterpret_cast<const uint4*>(g_kh + qkbase + (size_t)j * HD + c8);
                kl = *reinterpret_cast<const uint4*>(g_kl + qkbase + (size_t)j * HD + c8);
            }
            *reinterpret_cast<uint4*>(smem + OFF_KH + soff) = kh;
            *reinterpret_cast<uint4*>(smem + OFF_KL + soff) = kl;
            int j0 = kb + ch * 64 + c8;
            uint4 vh = make_uint4(0,0,0,0), vl = make_uint4(0,0,0,0);
            if (j0 >= 0 && j0 < Ssz) {
                vh = *reinterpret_cast<const uint4*>(g_vth + vbase + (size_t)row * Ssz + j0);
                vl = *reinterpret_cast<const uint4*>(g_vtl + vbase + (size_t)row * Ssz + j0);
            }
            *reinterpret_cast<uint4*>(smem + OFF_VH + soff) = vh;
            *reinterpret_cast<uint4*>(smem + OFF_VL + soff) = vl;
        }
        __syncthreads();

        // ---- S = Q K^T chunk (3-term split HMMA), into regs ----
        float s[4][4];
        #pragma unroll
        for (int nt = 0; nt < 4; nt++)
            #pragma unroll
            for (int e = 0; e < 4; e++) s[nt][e] = 0.f;

        #pragma unroll
        for (int ks = 0; ks < 4; ks++) {
            const int kk = ks * 16;
            uint32_t qh4[4], ql4[4], kh4[2][4], kl4[2][4];
            uint32_t aoff = (uint32_t)(arow * ARS + (kk + akd) * 2);
            ldm_x4(qh4, sbase + OFF_QH + aoff);
            ldm_x4(ql4, sbase + OFF_QL + aoff);
            #pragma unroll
            for (int g = 0; g < 2; g++) {
                uint32_t boff = (uint32_t)((wn + nrow8 + g * 16) * ARS + (kk + bkd) * 2);
                ldm_x4(kh4[g], sbase + OFF_KH + boff);
                ldm_x4(kl4[g], sbase + OFF_KL + boff);
            }
            #pragma unroll
            for (int nt = 0; nt < 4; nt++) {
                const uint32_t* b2h = &kh4[nt >> 1][(nt & 1) * 2];
                const uint32_t* b2l = &kl4[nt >> 1][(nt & 1) * 2];
                mma_bf16(s[nt], qh4, b2h);
                mma_bf16(s[nt], qh4, b2l);
                mma_bf16(s[nt], ql4, b2h);
            }
        }

        // ---- mask out-of-band / out-of-range, per-row chunk max ----
        float mx0 = -1e30f, mx1 = -1e30f;
        #pragma unroll
        for (int nt = 0; nt < 4; nt++) {
            #pragma unroll
            for (int e = 0; e < 2; e++) {
                const int C = ch * 64 + wn + nt * 8 + lc + e;
                const int j = kb + C;
                const bool jv = (j >= 0) && (j < Ssz);
                if (!(jv && C >= r0 && C <= r0 + 256))          s[nt][e]     = -1e30f;
                if (!(jv && C >= r0 + 8 && C <= r0 + 8 + 256))  s[nt][2 + e] = -1e30f;
                mx0 = fmaxf(mx0, s[nt][e]);
                mx1 = fmaxf(mx1, s[nt][2 + e]);
            }
        }
        mx0 = fmaxf(mx0, __shfl_xor_sync(0xffffffffu, mx0, 1));
        mx0 = fmaxf(mx0, __shfl_xor_sync(0xffffffffu, mx0, 2));
        mx1 = fmaxf(mx1, __shfl_xor_sync(0xffffffffu, mx1, 1));
        mx1 = fmaxf(mx1, __shfl_xor_sync(0xffffffffu, mx1, 2));
        if ((lane & 3) == 0) {
            stats[r0 * 2 + wnI]       = mx0;
            stats[(r0 + 8) * 2 + wnI] = mx1;
        }
        __syncthreads();

        // ---- merge running max, compute alpha, pre-scale running sum ----
        if (t < 64) {
            float mc = fmaxf(stats[t * 2], stats[t * 2 + 1]);
            float mo = m_run[t];
            float mn = fmaxf(mo, mc);
            float a  = __expf((mo - mn) * scale);
            alphv[t] = a;
            m_run[t] = mn;
            s_run[t] *= a;
        }
        __syncthreads();

        // ---- rescale acc2, compute P = exp((s-m)*scale), write bf16 hi/lo,
        //      accumulate row sums ----
        {
            const float a0 = alphv[r0], a1 = alphv[r0 + 8];
            #pragma unroll
            for (int nt = 0; nt < 4; nt++) {
                acc2[nt][0] *= a0; acc2[nt][1] *= a0;
                acc2[nt][2] *= a1; acc2[nt][3] *= a1;
            }
            const float mn0 = m_run[r0] * scale, mn1 = m_run[r0 + 8] * scale;
            float sum0 = 0.f, sum1 = 0.f;
            #pragma unroll
            for (int nt = 0; nt < 4; nt++) {
                const int colc = wn + nt * 8 + lc;
                float e0a = __expf(s[nt][0] * scale - mn0);
                float e0b = __expf(s[nt][1] * scale - mn0);
                float e1a = __expf(s[nt][2] * scale - mn1);
                float e1b = __expf(s[nt][3] * scale - mn1);
                sum0 += e0a + e0b;
                sum1 += e1a + e1b;
                __nv_bfloat16 h0a = __float2bfloat16(e0a), h0b = __float2bfloat16(e0b);
                __nv_bfloat16 h1a = __float2bfloat16(e1a), h1b = __float2bfloat16(e1b);
                *reinterpret_cast<__nv_bfloat162*>(smem + OFF_PH + r0 * ARS + colc * 2) =
                    __halves2bfloat162(h0a, h0b);
                *reinterpret_cast<__nv_bfloat162*>(smem + OFF_PL + r0 * ARS + colc * 2) =
                    __halves2bfloat162(__float2bfloat16(e0a - __bfloat162float(h0a)),
                                       __float2bfloat16(e0b - __bfloat162float(h0b)));
                *reinterpret_cast<__nv_bfloat162*>(smem + OFF_PH + (r0 + 8) * ARS + colc * 2) =
                    __halves2bfloat162(h1a, h1b);
                *reinterpret_cast<__nv_bfloat162*>(smem + OFF_PL + (r0 + 8) * ARS + colc * 2) =
                    __halves2bfloat162(__float2bfloat16(e1a - __bfloat162float(h1a)),
                                       __float2bfloat16(e1b - __bfloat162float(h1b)));
            }
            sum0 += __shfl_xor_sync(0xffffffffu, sum0, 1);
            sum0 += __shfl_xor_sync(0xffffffffu, sum0, 2);
            sum1 += __shfl_xor_sync(0xffffffffu, sum1, 1);
            sum1 += __shfl_xor_sync(0xffffffffu, sum1, 2);
            if ((lane & 3) == 0) {
                atomicAdd(&s_run[r0], sum0);
                atomicAdd(&s_run[r0 + 8], sum1);
            }
        }
        __syncthreads();

        // ---- PV: acc2 += P_chunk @ V_chunk (3-term split HMMA) ----
        #pragma unroll
        for (int ks = 0; ks < 4; ks++) {
            const int kk = ks * 16;
            uint32_t ph4[4], pl4[4], vh4[2][4], vl4[2][4];
            uint32_t aoff = (uint32_t)(arow * ARS + (kk + akd) * 2);
            ldm_x4(ph4, sbase + OFF_PH + aoff);
            ldm_x4(pl4, sbase + OFF_PL + aoff);
            #pragma unroll
            for (int g = 0; g < 2; g++) {
                uint32_t boff = (uint32_t)((wn + nrow8 + g * 16) * ARS + (kk + bkd) * 2);
                ldm_x4(vh4[g], sbase + OFF_VH + boff);
                ldm_x4(vl4[g], sbase + OFF_VL + boff);
            }
            #pragma unroll
            for (int nt = 0; nt < 4; nt++) {
                const uint32_t* b2h = &vh4[nt >> 1][(nt & 1) * 2];
                const uint32_t* b2l = &vl4[nt >> 1][(nt & 1) * 2];
                mma_bf16(acc2[nt], ph4, b2h);
                mma_bf16(acc2[nt], ph4, b2l);
                mma_bf16(acc2[nt], pl4, b2h);
            }
        }
    }
    __syncthreads();   // final atomicAdds visible

    // ---- epilogue: normalize, split bf16 hi/lo, write [m][EMB] ----
    #pragma unroll
    for (int half = 0; half < 2; half++) {
        const int r  = r0 + half * 8;
        const float is = 1.0f / s_run[r];
        const size_t rowbase = (size_t)(b * Ssz + qs + r) * EMB + h * HD;
        #pragma unroll
        for (int nt = 0; nt < 4; nt++) {
            #pragma unroll
            for (int e = 0; e < 2; e++) {
                const int d = wn + nt * 8 + lc + e;
                float val = acc2[nt][half * 2 + e] * is;
                __nv_bfloat16 vh = __float2bfloat16(val);
                g_avh[rowbase + d] = vh;
                g_avl[rowbase + d] = __float2bfloat16(val - __bfloat162float(vh));
            }
        }
    }
}

// ---------------------------------------------------------------------------
extern "C" void kernel_launch(void* const* d_in, const int* in_sizes, int n_in,
                              void* d_out, int out_size)
{
    const float* x    = (const float*)d_in[0];
    const int*   pm   = (const int*)  d_in[1];
    const float* Wqkv = (const float*)d_in[2];
    const float* bqkv = (const float*)d_in[3];
    const float* Wo   = (const float*)d_in[4];
    const float* bo   = (const float*)d_in[5];
    float* out = (float*)d_out;

    cudaFuncSetAttribute(attn_kernel,
                         cudaFuncAttributeMaxDynamicSharedMemorySize, ATTN_SMEM);
    cudaFuncSetAttribute(qkv_mma,
                         cudaFuncAttributeMaxDynamicSharedMemorySize, GEMM_SMEM);
    cudaFuncSetAttribute(out_mma,
                         cudaFuncAttributeMaxDynamicSharedMemorySize, GEMM_SMEM);

    split_x <<<(M1*INDIM/4 + 255)/256, 256>>>((const float4*)x);
    split_w <<<(N1*INDIM/4 + 255)/256, 256>>>((const float4*)Wqkv);
    split_wo<<<(EMB*EMB/4  + 255)/256, 256>>>((const float4*)Wo);

    qkv_mma<<<dim3(N1/128, M1/128), 256, GEMM_SMEM>>>(bqkv, pm);

    attn_kernel<<<dim3(Ssz/64, Bsz*NH), 256, ATTN_SMEM>>>();

    out_mma<<<dim3(EMB/128, M1/128), 256, GEMM_SMEM>>>(bo, out);
}

// round 11
// speedup vs baseline: 1.5021x; 1.2470x over previous
#include <cuda_runtime.h>
#include <cuda_bf16.h>
#include <cuda_fp16.h>
#include <math.h>
#include <cstdint>

#define Bsz   2
#define Ssz   2048
#define INDIM 1024
#define EMB   1024
#define NH    16
#define HD    64
#define PADW  128

#define M1 (Bsz*Ssz)   /* 4096 */
#define N1 (3*EMB)     /* 3072 */

// ---------------------------------------------------------------------------
// Baseline-ISA PTX helpers (compute_103-legal)
// ---------------------------------------------------------------------------
__device__ __forceinline__ uint32_t smem_to_u32(const void* p) {
    uint32_t a;
    asm("{ .reg .u64 t; cvta.to.shared.u64 t, %1; cvt.u32.u64 %0, t; }" : "=r"(a) : "l"(p));
    return a;
}
#define CP_ASYNC16(saddr, gptr) \
    asm volatile("cp.async.cg.shared.global [%0], [%1], 16;" :: "r"(saddr), "l"(gptr))
#define CP_COMMIT() asm volatile("cp.async.commit_group;" ::: "memory")
#define CP_WAIT1()  asm volatile("cp.async.wait_group 1;" ::: "memory")
#define CP_WAIT0()  asm volatile("cp.async.wait_group 0;" ::: "memory")

__device__ __forceinline__ void ldm_x4(uint32_t* r, uint32_t addr) {
    asm volatile("ldmatrix.sync.aligned.m8n8.x4.shared.b16 {%0,%1,%2,%3}, [%4];"
        : "=r"(r[0]), "=r"(r[1]), "=r"(r[2]), "=r"(r[3]) : "r"(addr));
}
__device__ __forceinline__ void mma_bf16(float* d, const uint32_t* a, const uint32_t* b) {
    asm volatile("mma.sync.aligned.m16n8k16.row.col.f32.bf16.bf16.f32 "
        "{%0,%1,%2,%3}, {%4,%5,%6,%7}, {%8,%9}, {%0,%1,%2,%3};"
        : "+f"(d[0]), "+f"(d[1]), "+f"(d[2]), "+f"(d[3])
        : "r"(a[0]), "r"(a[1]), "r"(a[2]), "r"(a[3]), "r"(b[0]), "r"(b[1]));
}
__device__ __forceinline__ void mma_fp16(float* d, const uint32_t* a, const uint32_t* b) {
    asm volatile("mma.sync.aligned.m16n8k16.row.col.f32.f16.f16.f32 "
        "{%0,%1,%2,%3}, {%4,%5,%6,%7}, {%8,%9}, {%0,%1,%2,%3};"
        : "+f"(d[0]), "+f"(d[1]), "+f"(d[2]), "+f"(d[3])
        : "r"(a[0]), "r"(a[1]), "r"(a[2]), "r"(a[3]), "r"(b[0]), "r"(b[1]));
}

// ---------------------------------------------------------------------------
// Scratch (static device globals)
// ---------------------------------------------------------------------------
// fp16 split-A + single-W operands for the projection GEMMs
__device__ __half g_xh16[M1*INDIM], g_xl16[M1*INDIM];
__device__ __half g_w16[N1*INDIM];
__device__ __half g_wo16[EMB*EMB];
__device__ __half g_avh16[M1*EMB], g_avl16[M1*EMB];
// bf16 3-term operands for attention (q,k: [b,h,s,d]; v^T: [b,h,d,s])
__device__ __nv_bfloat16 g_qh[Bsz*NH*Ssz*HD], g_ql[Bsz*NH*Ssz*HD];
__device__ __nv_bfloat16 g_kh[Bsz*NH*Ssz*HD], g_kl[Bsz*NH*Ssz*HD];
__device__ __nv_bfloat16 g_vth[Bsz*NH*HD*Ssz], g_vtl[Bsz*NH*HD*Ssz];

// ---------------------------------------------------------------------------
// Input conversion kernels
// ---------------------------------------------------------------------------
__global__ void split_x16(const float4* __restrict__ in) {
    int i = blockIdx.x * blockDim.x + threadIdx.x;
    if (i >= (M1*INDIM)/4) return;
    float4 f = in[i];
    __half h0 = __float2half_rn(f.x), h1 = __float2half_rn(f.y);
    __half h2 = __float2half_rn(f.z), h3 = __float2half_rn(f.w);
    __half2* H = (__half2*)g_xh16;
    __half2* L = (__half2*)g_xl16;
    H[2*i]   = __halves2half2(h0, h1);
    H[2*i+1] = __halves2half2(h2, h3);
    L[2*i]   = __halves2half2(__float2half_rn(f.x - __half2float(h0)),
                              __float2half_rn(f.y - __half2float(h1)));
    L[2*i+1] = __halves2half2(__float2half_rn(f.z - __half2float(h2)),
                              __float2half_rn(f.w - __half2float(h3)));
}
__global__ void conv_w16(const float4* __restrict__ in) {
    int i = blockIdx.x * blockDim.x + threadIdx.x;
    if (i >= (N1*INDIM)/4) return;
    float4 f = in[i];
    __half2* D = (__half2*)g_w16;
    D[2*i]   = __floats2half2_rn(f.x, f.y);
    D[2*i+1] = __floats2half2_rn(f.z, f.w);
}
__global__ void conv_wo16(const float4* __restrict__ in) {
    int i = blockIdx.x * blockDim.x + threadIdx.x;
    if (i >= (EMB*EMB)/4) return;
    float4 f = in[i];
    __half2* D = (__half2*)g_wo16;
    D[2*i]   = __floats2half2_rn(f.x, f.y);
    D[2*i+1] = __floats2half2_rn(f.z, f.w);
}

// ---------------------------------------------------------------------------
// fp16 2-term HMMA GEMM: CTA 128x128, BK=32, 8 warps (64x32 warp tile),
// 3-stage cp.async pipeline, ONE __syncthreads per chunk.
// Stage = {Ah, Al, W} tiles, 80 B smem rows. 92160 B total -> 2 CTAs/SM.
// ---------------------------------------------------------------------------
#define TILE_B 10240
#define STG_SZ (3 * TILE_B)       /* 30720 */
#define GEMM_SMEM (3 * STG_SZ)    /* 92160 */

__device__ __forceinline__ void load3_async(
    const __half* ah, const __half* al, const __half* bw,
    int m0, int n0, int k0, uint32_t sb, int stg, int t)
{
    uint32_t base = sb + stg * STG_SZ;
    #pragma unroll
    for (int i = 0; i < 2; i++) {
        int c  = t + i * 256;
        int r  = c >> 2;
        int kc = c & 3;
        size_t goffA = (size_t)(m0 + r) * 1024 + k0 + kc * 8;
        size_t goffB = (size_t)(n0 + r) * 1024 + k0 + kc * 8;
        uint32_t soff = (uint32_t)(r * 80 + kc * 16);
        CP_ASYNC16(base + soff,            ah + goffA);
        CP_ASYNC16(base + TILE_B + soff,   al + goffA);
        CP_ASYNC16(base + 2*TILE_B + soff, bw + goffB);
    }
}

__device__ __forceinline__ void gemm2_mainloop(
    const __half* __restrict__ ah, const __half* __restrict__ al,
    const __half* __restrict__ bw,
    int m0, int n0, uint32_t sb, int t, float acc[4][4][4])
{
    const int lane = t & 31, wid = t >> 5;
    const int wm = (wid >> 2) * 64, wn = (wid & 3) * 32;

    #pragma unroll
    for (int a = 0; a < 4; a++)
        #pragma unroll
        for (int b = 0; b < 4; b++)
            #pragma unroll
            for (int e = 0; e < 4; e++)
                acc[a][b][e] = 0.f;

    load3_async(ah, al, bw, m0, n0, 0,  sb, 0, t); CP_COMMIT();
    load3_async(ah, al, bw, m0, n0, 32, sb, 1, t); CP_COMMIT();

    const int arow = wm + (lane & 15);
    const int akd  = (lane & 16) >> 1;
    const int nrow = wn + (lane & 7) + ((lane & 16) >> 1);
    const int bkd  = (lane & 8);

    for (int ch = 0; ch < 32; ch++) {
        if (ch < 31) CP_WAIT1(); else CP_WAIT0();
        __syncthreads();
        if (ch + 2 < 32) {
            load3_async(ah, al, bw, m0, n0, (ch + 2) * 32, sb, (ch + 2) % 3, t);
            CP_COMMIT();
        }
        const uint32_t base = sb + (ch % 3) * STG_SZ;
        #pragma unroll
        for (int ks = 0; ks < 2; ks++) {
            const int kk = ks * 16;
            uint32_t ahf[4][4], alf[4][4], bwf[2][4];
            #pragma unroll
            for (int mt = 0; mt < 4; mt++) {
                uint32_t off = (uint32_t)((arow + mt * 16) * 80 + (kk + akd) * 2);
                ldm_x4(ahf[mt], base + off);
                ldm_x4(alf[mt], base + TILE_B + off);
            }
            #pragma unroll
            for (int g = 0; g < 2; g++) {
                uint32_t off = (uint32_t)((nrow + g * 16) * 80 + (kk + bkd) * 2);
                ldm_x4(bwf[g], base + 2*TILE_B + off);
            }
            #pragma unroll
            for (int mt = 0; mt < 4; mt++)
                #pragma unroll
                for (int nt = 0; nt < 4; nt++) {
                    const uint32_t* b2 = &bwf[nt >> 1][(nt & 1) * 2];
                    mma_fp16(acc[mt][nt], ahf[mt], b2);
                    mma_fp16(acc[mt][nt], alf[mt], b2);
                }
        }
    }
}

// QKV projection: bias + padding mask epilogue, split to bf16 hi/lo,
// scatter q,k [b,h,s,d] and v transposed [b,h,d,s].
__global__ __launch_bounds__(256) void qkv_mma(
    const float* __restrict__ bias, const int* __restrict__ pm)
{
    extern __shared__ __align__(16) char smem[];
    const uint32_t sb = smem_to_u32(smem);
    const int t = threadIdx.x, lane = t & 31, wid = t >> 5;
    const int wm = (wid >> 2) * 64, wn = (wid & 3) * 32;
    const int n0 = blockIdx.x * 128, m0 = blockIdx.y * 128;

    float acc[4][4][4];
    gemm2_mainloop(g_xh16, g_xl16, g_w16, m0, n0, sb, t, acc);

    const int lr = lane >> 2, lc = (lane & 3) * 2;
    #pragma unroll
    for (int mt = 0; mt < 4; mt++) {
        #pragma unroll
        for (int half = 0; half < 2; half++) {
            const int m = m0 + wm + mt * 16 + lr + half * 8;
            const int msk = pm[m];
            const int bb = m >> 11, s = m & 2047;
            #pragma unroll
            for (int nt = 0; nt < 4; nt++) {
                #pragma unroll
                for (int e = 0; e < 2; e++) {
                    const int n = n0 + wn + nt * 8 + lc + e;
                    float val = msk ? 0.0f : (acc[mt][nt][half * 2 + e] + bias[n]);
                    __nv_bfloat16 vh = __float2bfloat16(val);
                    __nv_bfloat16 vl = __float2bfloat16(val - __bfloat162float(vh));
                    int h  = n / 192;
                    int cc = n - h * 192;
                    if (cc < HD) {
                        int idx = ((bb * NH + h) * Ssz + s) * HD + cc;
                        g_qh[idx] = vh; g_ql[idx] = vl;
                    } else if (cc < 2*HD) {
                        int idx = ((bb * NH + h) * Ssz + s) * HD + cc - HD;
                        g_kh[idx] = vh; g_kl[idx] = vl;
                    } else {
                        int idx = ((bb * NH + h) * HD + cc - 2*HD) * Ssz + s;
                        g_vth[idx] = vh; g_vtl[idx] = vl;
                    }
                }
            }
        }
    }
}

// Output projection: out = attn_vals @ Wo^T + bo
__global__ __launch_bounds__(256) void out_mma(
    const float* __restrict__ bias, float* __restrict__ C)
{
    extern __shared__ __align__(16) char smem[];
    const uint32_t sb = smem_to_u32(smem);
    const int t = threadIdx.x, lane = t & 31, wid = t >> 5;
    const int wm = (wid >> 2) * 64, wn = (wid & 3) * 32;
    const int n0 = blockIdx.x * 128, m0 = blockIdx.y * 128;

    float acc[4][4][4];
    gemm2_mainloop(g_avh16, g_avl16, g_wo16, m0, n0, sb, t, acc);

    const int lr = lane >> 2, lc = (lane & 3) * 2;
    #pragma unroll
    for (int mt = 0; mt < 4; mt++) {
        #pragma unroll
        for (int half = 0; half < 2; half++) {
            const int m = m0 + wm + mt * 16 + lr + half * 8;
            #pragma unroll
            for (int nt = 0; nt < 4; nt++) {
                const int n = n0 + wn + nt * 8 + lc;
                float2 o;
                o.x = acc[mt][nt][half * 2 + 0] + bias[n];
                o.y = acc[mt][nt][half * 2 + 1] + bias[n + 1];
                *reinterpret_cast<float2*>(C + (size_t)m * EMB + n) = o;
            }
        }
    }
}

// ---------------------------------------------------------------------------
// Banded attention with online softmax (validated round 10; bf16 3-term).
// Epilogue now emits fp16 hi/lo for the out projection.
// ---------------------------------------------------------------------------
#define ARS  144
#define OFF_QH  0
#define OFF_QL  9216
#define OFF_KH  18432
#define OFF_KL  27648
#define OFF_VH  36864
#define OFF_VL  46080
#define OFF_PH  55296
#define OFF_PL  64512
#define OFF_MR  73728
#define OFF_SR  (OFF_MR + 256)
#define OFF_ALP (OFF_MR + 512)
#define OFF_ST  (OFF_MR + 768)
#define ATTN_SMEM (OFF_MR + 768 + 512)

__global__ __launch_bounds__(256, 2) void attn_kernel()
{
    extern __shared__ __align__(16) char smem[];
    const uint32_t sbase = smem_to_u32(smem);
    float* m_run = (float*)(smem + OFF_MR);
    float* s_run = (float*)(smem + OFF_SR);
    float* alphv = (float*)(smem + OFF_ALP);
    float* stats = (float*)(smem + OFF_ST);

    const int t = threadIdx.x, lane = t & 31, w = t >> 5;
    const int b  = blockIdx.y >> 4, h = blockIdx.y & 15;
    const int qs = blockIdx.x * 64;
    const int kb = qs - PADW;

    const size_t qkbase = (size_t)(b * NH + h) * Ssz * HD;
    const size_t vbase  = (size_t)(b * NH + h) * HD * Ssz;

    const int wm4 = (w >> 1) << 4;
    const int wnI = w & 1;
    const int wn  = wnI << 5;
    const int arow = wm4 + (lane & 15);
    const int akd  = (lane & 16) >> 1;
    const int nrow8 = (lane & 7) + ((lane & 16) >> 1);
    const int bkd  = (lane & 8);
    const int lr = lane >> 2, lc = (lane & 3) * 2;
    const int r0 = wm4 + lr;
    const float scale = 0.125f;

    if (t < 64) { m_run[t] = -1e30f; s_run[t] = 0.f; }
    #pragma unroll
    for (int i = 0; i < 2; i++) {
        int u = t + i * 256;
        int row = u >> 3;
        int c8  = (u & 7) * 8;
        uint32_t soff = (uint32_t)(row * ARS + c8 * 2);
        *reinterpret_cast<uint4*>(smem + OFF_QH + soff) =
            *reinterpret_cast<const uint4*>(g_qh + qkbase + (size_t)(qs + row) * HD + c8);
        *reinterpret_cast<uint4*>(smem + OFF_QL + soff) =
            *reinterpret_cast<const uint4*>(g_ql + qkbase + (size_t)(qs + row) * HD + c8);
    }

    float acc2[4][4];
    #pragma unroll
    for (int nt = 0; nt < 4; nt++)
        #pragma unroll
        for (int e = 0; e < 4; e++) acc2[nt][e] = 0.f;

    for (int ch = 0; ch < 5; ch++) {
        __syncthreads();
        #pragma unroll
        for (int i = 0; i < 2; i++) {
            int u   = t + i * 256;
            int row = u >> 3;
            int c8  = (u & 7) * 8;
            uint32_t soff = (uint32_t)(row * ARS + c8 * 2);
            int j = kb + ch * 64 + row;
            uint4 kh = make_uint4(0,0,0,0), kl = make_uint4(0,0,0,0);
            if (j >= 0 && j < Ssz) {
                kh = *reinterpret_cast<const uint4*>(g_kh + qkbase + (size_t)j * HD + c8);
                kl = *reinterpret_cast<const uint4*>(g_kl + qkbase + (size_t)j * HD + c8);
            }
            *reinterpret_cast<uint4*>(smem + OFF_KH + soff) = kh;
            *reinterpret_cast<uint4*>(smem + OFF_KL + soff) = kl;
            int j0 = kb + ch * 64 + c8;
            uint4 vh = make_uint4(0,0,0,0), vl = make_uint4(0,0,0,0);
            if (j0 >= 0 && j0 < Ssz) {
                vh = *reinterpret_cast<const uint4*>(g_vth + vbase + (size_t)row * Ssz + j0);
                vl = *reinterpret_cast<const uint4*>(g_vtl + vbase + (size_t)row * Ssz + j0);
            }
            *reinterpret_cast<uint4*>(smem + OFF_VH + soff) = vh;
            *reinterpret_cast<uint4*>(smem + OFF_VL + soff) = vl;
        }
        __syncthreads();

        float s[4][4];
        #pragma unroll
        for (int nt = 0; nt < 4; nt++)
            #pragma unroll
            for (int e = 0; e < 4; e++) s[nt][e] = 0.f;

        #pragma unroll
        for (int ks = 0; ks < 4; ks++) {
            const int kk = ks * 16;
            uint32_t qh4[4], ql4[4], kh4[2][4], kl4[2][4];
            uint32_t aoff = (uint32_t)(arow * ARS + (kk + akd) * 2);
            ldm_x4(qh4, sbase + OFF_QH + aoff);
            ldm_x4(ql4, sbase + OFF_QL + aoff);
            #pragma unroll
            for (int g = 0; g < 2; g++) {
                uint32_t boff = (uint32_t)((wn + nrow8 + g * 16) * ARS + (kk + bkd) * 2);
                ldm_x4(kh4[g], sbase + OFF_KH + boff);
                ldm_x4(kl4[g], sbase + OFF_KL + boff);
            }
            #pragma unroll
            for (int nt = 0; nt < 4; nt++) {
                const uint32_t* b2h = &kh4[nt >> 1][(nt & 1) * 2];
                const uint32_t* b2l = &kl4[nt >> 1][(nt & 1) * 2];
                mma_bf16(s[nt], qh4, b2h);
                mma_bf16(s[nt], qh4, b2l);
                mma_bf16(s[nt], ql4, b2h);
            }
        }

        float mx0 = -1e30f, mx1 = -1e30f;
        #pragma unroll
        for (int nt = 0; nt < 4; nt++) {
            #pragma unroll
            for (int e = 0; e < 2; e++) {
                const int C = ch * 64 + wn + nt * 8 + lc + e;
                const int j = kb + C;
                const bool jv = (j >= 0) && (j < Ssz);
                if (!(jv && C >= r0 && C <= r0 + 256))          s[nt][e]     = -1e30f;
                if (!(jv && C >= r0 + 8 && C <= r0 + 8 + 256))  s[nt][2 + e] = -1e30f;
                mx0 = fmaxf(mx0, s[nt][e]);
                mx1 = fmaxf(mx1, s[nt][2 + e]);
            }
        }
        mx0 = fmaxf(mx0, __shfl_xor_sync(0xffffffffu, mx0, 1));
        mx0 = fmaxf(mx0, __shfl_xor_sync(0xffffffffu, mx0, 2));
        mx1 = fmaxf(mx1, __shfl_xor_sync(0xffffffffu, mx1, 1));
        mx1 = fmaxf(mx1, __shfl_xor_sync(0xffffffffu, mx1, 2));
        if ((lane & 3) == 0) {
            stats[r0 * 2 + wnI]       = mx0;
            stats[(r0 + 8) * 2 + wnI] = mx1;
        }
        __syncthreads();

        if (t < 64) {
            float mc = fmaxf(stats[t * 2], stats[t * 2 + 1]);
            float mo = m_run[t];
            float mn = fmaxf(mo, mc);
            float a  = __expf((mo - mn) * scale);
            alphv[t] = a;
            m_run[t] = mn;
            s_run[t] *= a;
        }
        __syncthreads();

        {
            const float a0 = alphv[r0], a1 = alphv[r0 + 8];
            #pragma unroll
            for (int nt = 0; nt < 4; nt++) {
                acc2[nt][0] *= a0; acc2[nt][1] *= a0;
                acc2[nt][2] *= a1; acc2[nt][3] *= a1;
            }
            const float mn0 = m_run[r0] * scale, mn1 = m_run[r0 + 8] * scale;
            float sum0 = 0.f, sum1 = 0.f;
            #pragma unroll
            for (int nt = 0; nt < 4; nt++) {
                const int colc = wn + nt * 8 + lc;
                float e0a = __expf(s[nt][0] * scale - mn0);
                float e0b = __expf(s[nt][1] * scale - mn0);
                float e1a = __expf(s[nt][2] * scale - mn1);
                float e1b = __expf(s[nt][3] * scale - mn1);
                sum0 += e0a + e0b;
                sum1 += e1a + e1b;
                __nv_bfloat16 h0a = __float2bfloat16(e0a), h0b = __float2bfloat16(e0b);
                __nv_bfloat16 h1a = __float2bfloat16(e1a), h1b = __float2bfloat16(e1b);
                *reinterpret_cast<__nv_bfloat162*>(smem + OFF_PH + r0 * ARS + colc * 2) =
                    __halves2bfloat162(h0a, h0b);
                *reinterpret_cast<__nv_bfloat162*>(smem + OFF_PL + r0 * ARS + colc * 2) =
                    __halves2bfloat162(__float2bfloat16(e0a - __bfloat162float(h0a)),
                                       __float2bfloat16(e0b - __bfloat162float(h0b)));
                *reinterpret_cast<__nv_bfloat162*>(smem + OFF_PH + (r0 + 8) * ARS + colc * 2) =
                    __halves2bfloat162(h1a, h1b);
                *reinterpret_cast<__nv_bfloat162*>(smem + OFF_PL + (r0 + 8) * ARS + colc * 2) =
                    __halves2bfloat162(__float2bfloat16(e1a - __bfloat162float(h1a)),
                                       __float2bfloat16(e1b - __bfloat162float(h1b)));
            }
            sum0 += __shfl_xor_sync(0xffffffffu, sum0, 1);
            sum0 += __shfl_xor_sync(0xffffffffu, sum0, 2);
            sum1 += __shfl_xor_sync(0xffffffffu, sum1, 1);
            sum1 += __shfl_xor_sync(0xffffffffu, sum1, 2);
            if ((lane & 3) == 0) {
                atomicAdd(&s_run[r0], sum0);
                atomicAdd(&s_run[r0 + 8], sum1);
            }
        }
        __syncthreads();

        #pragma unroll
        for (int ks = 0; ks < 4; ks++) {
            const int kk = ks * 16;
            uint32_t ph4[4], pl4[4], vh4[2][4], vl4[2][4];
            uint32_t aoff = (uint32_t)(arow * ARS + (kk + akd) * 2);
            ldm_x4(ph4, sbase + OFF_PH + aoff);
            ldm_x4(pl4, sbase + OFF_PL + aoff);
            #pragma unroll
            for (int g = 0; g < 2; g++) {
                uint32_t boff = (uint32_t)((wn + nrow8 + g * 16) * ARS + (kk + bkd) * 2);
                ldm_x4(vh4[g], sbase + OFF_VH + boff);
                ldm_x4(vl4[g], sbase + OFF_VL + boff);
            }
            #pragma unroll
            for (int nt = 0; nt < 4; nt++) {
                const uint32_t* b2h = &vh4[nt >> 1][(nt & 1) * 2];
                const uint32_t* b2l = &vl4[nt >> 1][(nt & 1) * 2];
                mma_bf16(acc2[nt], ph4, b2h);
                mma_bf16(acc2[nt], ph4, b2l);
                mma_bf16(acc2[nt], pl4, b2h);
            }
        }
    }
    __syncthreads();

    // epilogue: normalize, split to fp16 hi/lo for the out projection
    #pragma unroll
    for (int half = 0; half < 2; half++) {
        const int r  = r0 + half * 8;
        const float is = 1.0f / s_run[r];
        const size_t rowbase = (size_t)(b * Ssz + qs + r) * EMB + h * HD;
        #pragma unroll
        for (int nt = 0; nt < 4; nt++) {
            #pragma unroll
            for (int e = 0; e < 2; e++) {
                const int d = wn + nt * 8 + lc + e;
                float val = acc2[nt][half * 2 + e] * is;
                __half vh = __float2half_rn(val);
                g_avh16[rowbase + d] = vh;
                g_avl16[rowbase + d] = __float2half_rn(val - __half2float(vh));
            }
        }
    }
}

// ---------------------------------------------------------------------------
extern "C" void kernel_launch(void* const* d_in, const int* in_sizes, int n_in,
                              void* d_out, int out_size)
{
    const float* x    = (const float*)d_in[0];
    const int*   pm   = (const int*)  d_in[1];
    const float* Wqkv = (const float*)d_in[2];
    const float* bqkv = (const float*)d_in[3];
    const float* Wo   = (const float*)d_in[4];
    const float* bo   = (const float*)d_in[5];
    float* out = (float*)d_out;

    cudaFuncSetAttribute(attn_kernel,
                         cudaFuncAttributeMaxDynamicSharedMemorySize, ATTN_SMEM);
    cudaFuncSetAttribute(qkv_mma,
                         cudaFuncAttributeMaxDynamicSharedMemorySize, GEMM_SMEM);
    cudaFuncSetAttribute(out_mma,
                         cudaFuncAttributeMaxDynamicSharedMemorySize, GEMM_SMEM);

    split_x16<<<(M1*INDIM/4 + 255)/256, 256>>>((const float4*)x);
    conv_w16 <<<(N1*INDIM/4 + 255)/256, 256>>>((const float4*)Wqkv);
    conv_wo16<<<(EMB*EMB/4  + 255)/256, 256>>>((const float4*)Wo);

    qkv_mma<<<dim3(N1/128, M1/128), 256, GEMM_SMEM>>>(bqkv, pm);

    attn_kernel<<<dim3(Ssz/64, Bsz*NH), 256, ATTN_SMEM>>>();

    out_mma<<<dim3(EMB/128, M1/128), 256, GEMM_SMEM>>>(bo, out);
}

// round 12
// speedup vs baseline: 1.9270x; 1.2829x over previous
#include <cuda_runtime.h>
#include <cuda_bf16.h>
#include <cuda_fp16.h>
#include <math.h>
#include <cstdint>

#define Bsz   2
#define Ssz   2048
#define INDIM 1024
#define EMB   1024
#define NH    16
#define HD    64
#define PADW  128

#define M1 (Bsz*Ssz)   /* 4096 */
#define N1 (3*EMB)     /* 3072 */

// ---------------------------------------------------------------------------
// Baseline-ISA PTX helpers (compute_103-legal)
// ---------------------------------------------------------------------------
__device__ __forceinline__ uint32_t smem_to_u32(const void* p) {
    uint32_t a;
    asm("{ .reg .u64 t; cvta.to.shared.u64 t, %1; cvt.u32.u64 %0, t; }" : "=r"(a) : "l"(p));
    return a;
}
#define CP_ASYNC16(saddr, gptr) \
    asm volatile("cp.async.cg.shared.global [%0], [%1], 16;" :: "r"(saddr), "l"(gptr))
#define CP_COMMIT() asm volatile("cp.async.commit_group;" ::: "memory")
#define CP_WAIT1()  asm volatile("cp.async.wait_group 1;" ::: "memory")
#define CP_WAIT0()  asm volatile("cp.async.wait_group 0;" ::: "memory")

__device__ __forceinline__ void ldm_x4(uint32_t* r, uint32_t addr) {
    asm volatile("ldmatrix.sync.aligned.m8n8.x4.shared.b16 {%0,%1,%2,%3}, [%4];"
        : "=r"(r[0]), "=r"(r[1]), "=r"(r[2]), "=r"(r[3]) : "r"(addr));
}
__device__ __forceinline__ void mma_bf16(float* d, const uint32_t* a, const uint32_t* b) {
    asm volatile("mma.sync.aligned.m16n8k16.row.col.f32.bf16.bf16.f32 "
        "{%0,%1,%2,%3}, {%4,%5,%6,%7}, {%8,%9}, {%0,%1,%2,%3};"
        : "+f"(d[0]), "+f"(d[1]), "+f"(d[2]), "+f"(d[3])
        : "r"(a[0]), "r"(a[1]), "r"(a[2]), "r"(a[3]), "r"(b[0]), "r"(b[1]));
}
__device__ __forceinline__ void mma_fp16(float* d, const uint32_t* a, const uint32_t* b) {
    asm volatile("mma.sync.aligned.m16n8k16.row.col.f32.f16.f16.f32 "
        "{%0,%1,%2,%3}, {%4,%5,%6,%7}, {%8,%9}, {%0,%1,%2,%3};"
        : "+f"(d[0]), "+f"(d[1]), "+f"(d[2]), "+f"(d[3])
        : "r"(a[0]), "r"(a[1]), "r"(a[2]), "r"(a[3]), "r"(b[0]), "r"(b[1]));
}

// ---------------------------------------------------------------------------
// Scratch (static device globals)
// ---------------------------------------------------------------------------
__device__ __half g_x16[M1*INDIM];
__device__ __half g_w16[N1*INDIM];
__device__ __half g_wo16[EMB*EMB];
__device__ __half g_av16[M1*EMB];
// bf16 3-term operands for attention (q,k: [b,h,s,d]; v^T: [b,h,d,s])
__device__ __nv_bfloat16 g_qh[Bsz*NH*Ssz*HD], g_ql[Bsz*NH*Ssz*HD];
__device__ __nv_bfloat16 g_kh[Bsz*NH*Ssz*HD], g_kl[Bsz*NH*Ssz*HD];
__device__ __nv_bfloat16 g_vth[Bsz*NH*HD*Ssz], g_vtl[Bsz*NH*HD*Ssz];

// ---------------------------------------------------------------------------
// fp32 -> fp16 conversion kernels
// ---------------------------------------------------------------------------
__global__ void conv_x16(const float4* __restrict__ in) {
    int i = blockIdx.x * blockDim.x + threadIdx.x;
    if (i >= (M1*INDIM)/4) return;
    float4 f = in[i];
    __half2* D = (__half2*)g_x16;
    D[2*i]   = __floats2half2_rn(f.x, f.y);
    D[2*i+1] = __floats2half2_rn(f.z, f.w);
}
__global__ void conv_w16(const float4* __restrict__ in) {
    int i = blockIdx.x * blockDim.x + threadIdx.x;
    if (i >= (N1*INDIM)/4) return;
    float4 f = in[i];
    __half2* D = (__half2*)g_w16;
    D[2*i]   = __floats2half2_rn(f.x, f.y);
    D[2*i+1] = __floats2half2_rn(f.z, f.w);
}
__global__ void conv_wo16(const float4* __restrict__ in) {
    int i = blockIdx.x * blockDim.x + threadIdx.x;
    if (i >= (EMB*EMB)/4) return;
    float4 f = in[i];
    __half2* D = (__half2*)g_wo16;
    D[2*i]   = __floats2half2_rn(f.x, f.y);
    D[2*i+1] = __floats2half2_rn(f.z, f.w);
}

// ---------------------------------------------------------------------------
// Single-fp16 HMMA GEMM: CTA 128x128, BK=32, 8 warps (64x32 warp tile),
// 3-stage cp.async pipeline, one __syncthreads per chunk.
// Stage = {A, W} tiles, 80 B smem rows, 61440 B total.
// ---------------------------------------------------------------------------
#define TILE_B 10240
#define STG_SZ (2 * TILE_B)       /* 20480 */
#define GEMM_SMEM (3 * STG_SZ)    /* 61440 */

__device__ __forceinline__ void load2_async(
    const __half* a, const __half* bw,
    int m0, int n0, int k0, uint32_t sb, int stg, int t)
{
    uint32_t base = sb + stg * STG_SZ;
    #pragma unroll
    for (int i = 0; i < 2; i++) {
        int c  = t + i * 256;
        int r  = c >> 2;
        int kc = c & 3;
        size_t goffA = (size_t)(m0 + r) * 1024 + k0 + kc * 8;
        size_t goffB = (size_t)(n0 + r) * 1024 + k0 + kc * 8;
        uint32_t soff = (uint32_t)(r * 80 + kc * 16);
        CP_ASYNC16(base + soff,          a  + goffA);
        CP_ASYNC16(base + TILE_B + soff, bw + goffB);
    }
}

__device__ __forceinline__ void gemm1_mainloop(
    const __half* __restrict__ a, const __half* __restrict__ bw,
    int m0, int n0, uint32_t sb, int t, float acc[4][4][4])
{
    const int lane = t & 31, wid = t >> 5;
    const int wm = (wid >> 2) * 64, wn = (wid & 3) * 32;

    #pragma unroll
    for (int x = 0; x < 4; x++)
        #pragma unroll
        for (int y = 0; y < 4; y++)
            #pragma unroll
            for (int e = 0; e < 4; e++)
                acc[x][y][e] = 0.f;

    load2_async(a, bw, m0, n0, 0,  sb, 0, t); CP_COMMIT();
    load2_async(a, bw, m0, n0, 32, sb, 1, t); CP_COMMIT();

    const int arow = wm + (lane & 15);
    const int akd  = (lane & 16) >> 1;
    const int nrow = wn + (lane & 7) + ((lane & 16) >> 1);
    const int bkd  = (lane & 8);

    for (int ch = 0; ch < 32; ch++) {
        if (ch < 31) CP_WAIT1(); else CP_WAIT0();
        __syncthreads();
        if (ch + 2 < 32) {
            load2_async(a, bw, m0, n0, (ch + 2) * 32, sb, (ch + 2) % 3, t);
            CP_COMMIT();
        }
        const uint32_t base = sb + (ch % 3) * STG_SZ;
        #pragma unroll
        for (int ks = 0; ks < 2; ks++) {
            const int kk = ks * 16;
            uint32_t af[4][4], bwf[2][4];
            #pragma unroll
            for (int mt = 0; mt < 4; mt++) {
                uint32_t off = (uint32_t)((arow + mt * 16) * 80 + (kk + akd) * 2);
                ldm_x4(af[mt], base + off);
            }
            #pragma unroll
            for (int g = 0; g < 2; g++) {
                uint32_t off = (uint32_t)((nrow + g * 16) * 80 + (kk + bkd) * 2);
                ldm_x4(bwf[g], base + TILE_B + off);
            }
            #pragma unroll
            for (int mt = 0; mt < 4; mt++)
                #pragma unroll
                for (int nt = 0; nt < 4; nt++) {
                    const uint32_t* b2 = &bwf[nt >> 1][(nt & 1) * 2];
                    mma_fp16(acc[mt][nt], af[mt], b2);
                }
        }
    }
}

// QKV projection: bias + padding mask epilogue, split to bf16 hi/lo,
// scatter q,k [b,h,s,d] and v transposed [b,h,d,s].
__global__ __launch_bounds__(256) void qkv_mma(
    const float* __restrict__ bias, const int* __restrict__ pm)
{
    extern __shared__ __align__(16) char smem[];
    const uint32_t sb = smem_to_u32(smem);
    const int t = threadIdx.x, lane = t & 31, wid = t >> 5;
    const int wm = (wid >> 2) * 64, wn = (wid & 3) * 32;
    const int n0 = blockIdx.x * 128, m0 = blockIdx.y * 128;

    float acc[4][4][4];
    gemm1_mainloop(g_x16, g_w16, m0, n0, sb, t, acc);

    const int lr = lane >> 2, lc = (lane & 3) * 2;
    #pragma unroll
    for (int mt = 0; mt < 4; mt++) {
        #pragma unroll
        for (int half = 0; half < 2; half++) {
            const int m = m0 + wm + mt * 16 + lr + half * 8;
            const int msk = pm[m];
            const int bb = m >> 11, s = m & 2047;
            #pragma unroll
            for (int nt = 0; nt < 4; nt++) {
                #pragma unroll
                for (int e = 0; e < 2; e++) {
                    const int n = n0 + wn + nt * 8 + lc + e;
                    float val = msk ? 0.0f : (acc[mt][nt][half * 2 + e] + bias[n]);
                    __nv_bfloat16 vh = __float2bfloat16(val);
                    __nv_bfloat16 vl = __float2bfloat16(val - __bfloat162float(vh));
                    int h  = n / 192;
                    int cc = n - h * 192;
                    if (cc < HD) {
                        int idx = ((bb * NH + h) * Ssz + s) * HD + cc;
                        g_qh[idx] = vh; g_ql[idx] = vl;
                    } else if (cc < 2*HD) {
                        int idx = ((bb * NH + h) * Ssz + s) * HD + cc - HD;
                        g_kh[idx] = vh; g_kl[idx] = vl;
                    } else {
                        int idx = ((bb * NH + h) * HD + cc - 2*HD) * Ssz + s;
                        g_vth[idx] = vh; g_vtl[idx] = vl;
                    }
                }
            }
        }
    }
}

// Output projection: out = attn_vals @ Wo^T + bo
__global__ __launch_bounds__(256) void out_mma(
    const float* __restrict__ bias, float* __restrict__ C)
{
    extern __shared__ __align__(16) char smem[];
    const uint32_t sb = smem_to_u32(smem);
    const int t = threadIdx.x, lane = t & 31, wid = t >> 5;
    const int wm = (wid >> 2) * 64, wn = (wid & 3) * 32;
    const int n0 = blockIdx.x * 128, m0 = blockIdx.y * 128;

    float acc[4][4][4];
    gemm1_mainloop(g_av16, g_wo16, m0, n0, sb, t, acc);

    const int lr = lane >> 2, lc = (lane & 3) * 2;
    #pragma unroll
    for (int mt = 0; mt < 4; mt++) {
        #pragma unroll
        for (int half = 0; half < 2; half++) {
            const int m = m0 + wm + mt * 16 + lr + half * 8;
            #pragma unroll
            for (int nt = 0; nt < 4; nt++) {
                const int n = n0 + wn + nt * 8 + lc;
                float2 o;
                o.x = acc[mt][nt][half * 2 + 0] + bias[n];
                o.y = acc[mt][nt][half * 2 + 1] + bias[n + 1];
                *reinterpret_cast<float2*>(C + (size_t)m * EMB + n) = o;
            }
        }
    }
}

// ---------------------------------------------------------------------------
// Banded attention with online softmax (validated round 10/11; bf16 3-term).
// Epilogue emits single fp16 for the out projection.
// ---------------------------------------------------------------------------
#define ARS  144
#define OFF_QH  0
#define OFF_QL  9216
#define OFF_KH  18432
#define OFF_KL  27648
#define OFF_VH  36864
#define OFF_VL  46080
#define OFF_PH  55296
#define OFF_PL  64512
#define OFF_MR  73728
#define OFF_SR  (OFF_MR + 256)
#define OFF_ALP (OFF_MR + 512)
#define OFF_ST  (OFF_MR + 768)
#define ATTN_SMEM (OFF_MR + 768 + 512)

__global__ __launch_bounds__(256, 2) void attn_kernel()
{
    extern __shared__ __align__(16) char smem[];
    const uint32_t sbase = smem_to_u32(smem);
    float* m_run = (float*)(smem + OFF_MR);
    float* s_run = (float*)(smem + OFF_SR);
    float* alphv = (float*)(smem + OFF_ALP);
    float* stats = (float*)(smem + OFF_ST);

    const int t = threadIdx.x, lane = t & 31, w = t >> 5;
    const int b  = blockIdx.y >> 4, h = blockIdx.y & 15;
    const int qs = blockIdx.x * 64;
    const int kb = qs - PADW;

    const size_t qkbase = (size_t)(b * NH + h) * Ssz * HD;
    const size_t vbase  = (size_t)(b * NH + h) * HD * Ssz;

    const int wm4 = (w >> 1) << 4;
    const int wnI = w & 1;
    const int wn  = wnI << 5;
    const int arow = wm4 + (lane & 15);
    const int akd  = (lane & 16) >> 1;
    const int nrow8 = (lane & 7) + ((lane & 16) >> 1);
    const int bkd  = (lane & 8);
    const int lr = lane >> 2, lc = (lane & 3) * 2;
    const int r0 = wm4 + lr;
    const float scale = 0.125f;

    if (t < 64) { m_run[t] = -1e30f; s_run[t] = 0.f; }
    #pragma unroll
    for (int i = 0; i < 2; i++) {
        int u = t + i * 256;
        int row = u >> 3;
        int c8  = (u & 7) * 8;
        uint32_t soff = (uint32_t)(row * ARS + c8 * 2);
        *reinterpret_cast<uint4*>(smem + OFF_QH + soff) =
            *reinterpret_cast<const uint4*>(g_qh + qkbase + (size_t)(qs + row) * HD + c8);
        *reinterpret_cast<uint4*>(smem + OFF_QL + soff) =
            *reinterpret_cast<const uint4*>(g_ql + qkbase + (size_t)(qs + row) * HD + c8);
    }

    float acc2[4][4];
    #pragma unroll
    for (int nt = 0; nt < 4; nt++)
        #pragma unroll
        for (int e = 0; e < 4; e++) acc2[nt][e] = 0.f;

    for (int ch = 0; ch < 5; ch++) {
        __syncthreads();
        #pragma unroll
        for (int i = 0; i < 2; i++) {
            int u   = t + i * 256;
            int row = u >> 3;
            int c8  = (u & 7) * 8;
            uint32_t soff = (uint32_t)(row * ARS + c8 * 2);
            int j = kb + ch * 64 + row;
            uint4 kh = make_uint4(0,0,0,0), kl = make_uint4(0,0,0,0);
            if (j >= 0 && j < Ssz) {
                kh = *reinterpret_cast<const uint4*>(g_kh + qkbase + (size_t)j * HD + c8);
                kl = *reinterpret_cast<const uint4*>(g_kl + qkbase + (size_t)j * HD + c8);
            }
            *reinterpret_cast<uint4*>(smem + OFF_KH + soff) = kh;
            *reinterpret_cast<uint4*>(smem + OFF_KL + soff) = kl;
            int j0 = kb + ch * 64 + c8;
            uint4 vh = make_uint4(0,0,0,0), vl = make_uint4(0,0,0,0);
            if (j0 >= 0 && j0 < Ssz) {
                vh = *reinterpret_cast<const uint4*>(g_vth + vbase + (size_t)row * Ssz + j0);
                vl = *reinterpret_cast<const uint4*>(g_vtl + vbase + (size_t)row * Ssz + j0);
            }
            *reinterpret_cast<uint4*>(smem + OFF_VH + soff) = vh;
            *reinterpret_cast<uint4*>(smem + OFF_VL + soff) = vl;
        }
        __syncthreads();

        float s[4][4];
        #pragma unroll
        for (int nt = 0; nt < 4; nt++)
            #pragma unroll
            for (int e = 0; e < 4; e++) s[nt][e] = 0.f;

        #pragma unroll
        for (int ks = 0; ks < 4; ks++) {
            const int kk = ks * 16;
            uint32_t qh4[4], ql4[4], kh4[2][4], kl4[2][4];
            uint32_t aoff = (uint32_t)(arow * ARS + (kk + akd) * 2);
            ldm_x4(qh4, sbase + OFF_QH + aoff);
            ldm_x4(ql4, sbase + OFF_QL + aoff);
            #pragma unroll
            for (int g = 0; g < 2; g++) {
                uint32_t boff = (uint32_t)((wn + nrow8 + g * 16) * ARS + (kk + bkd) * 2);
                ldm_x4(kh4[g], sbase + OFF_KH + boff);
                ldm_x4(kl4[g], sbase + OFF_KL + boff);
            }
            #pragma unroll
            for (int nt = 0; nt < 4; nt++) {
                const uint32_t* b2h = &kh4[nt >> 1][(nt & 1) * 2];
                const uint32_t* b2l = &kl4[nt >> 1][(nt & 1) * 2];
                mma_bf16(s[nt], qh4, b2h);
                mma_bf16(s[nt], qh4, b2l);
                mma_bf16(s[nt], ql4, b2h);
            }
        }

        float mx0 = -1e30f, mx1 = -1e30f;
        #pragma unroll
        for (int nt = 0; nt < 4; nt++) {
            #pragma unroll
            for (int e = 0; e < 2; e++) {
                const int C = ch * 64 + wn + nt * 8 + lc + e;
                const int j = kb + C;
                const bool jv = (j >= 0) && (j < Ssz);
                if (!(jv && C >= r0 && C <= r0 + 256))          s[nt][e]     = -1e30f;
                if (!(jv && C >= r0 + 8 && C <= r0 + 8 + 256))  s[nt][2 + e] = -1e30f;
                mx0 = fmaxf(mx0, s[nt][e]);
                mx1 = fmaxf(mx1, s[nt][2 + e]);
            }
        }
        mx0 = fmaxf(mx0, __shfl_xor_sync(0xffffffffu, mx0, 1));
        mx0 = fmaxf(mx0, __shfl_xor_sync(0xffffffffu, mx0, 2));
        mx1 = fmaxf(mx1, __shfl_xor_sync(0xffffffffu, mx1, 1));
        mx1 = fmaxf(mx1, __shfl_xor_sync(0xffffffffu, mx1, 2));
        if ((lane & 3) == 0) {
            stats[r0 * 2 + wnI]       = mx0;
            stats[(r0 + 8) * 2 + wnI] = mx1;
        }
        __syncthreads();

        if (t < 64) {
            float mc = fmaxf(stats[t * 2], stats[t * 2 + 1]);
            float mo = m_run[t];
            float mn = fmaxf(mo, mc);
            float a  = __expf((mo - mn) * scale);
            alphv[t] = a;
            m_run[t] = mn;
            s_run[t] *= a;
        }
        __syncthreads();

        {
            const float a0 = alphv[r0], a1 = alphv[r0 + 8];
            #pragma unroll
            for (int nt = 0; nt < 4; nt++) {
                acc2[nt][0] *= a0; acc2[nt][1] *= a0;
                acc2[nt][2] *= a1; acc2[nt][3] *= a1;
            }
            const float mn0 = m_run[r0] * scale, mn1 = m_run[r0 + 8] * scale;
            float sum0 = 0.f, sum1 = 0.f;
            #pragma unroll
            for (int nt = 0; nt < 4; nt++) {
                const int colc = wn + nt * 8 + lc;
                float e0a = __expf(s[nt][0] * scale - mn0);
                float e0b = __expf(s[nt][1] * scale - mn0);
                float e1a = __expf(s[nt][2] * scale - mn1);
                float e1b = __expf(s[nt][3] * scale - mn1);
                sum0 += e0a + e0b;
                sum1 += e1a + e1b;
                __nv_bfloat16 h0a = __float2bfloat16(e0a), h0b = __float2bfloat16(e0b);
                __nv_bfloat16 h1a = __float2bfloat16(e1a), h1b = __float2bfloat16(e1b);
                *reinterpret_cast<__nv_bfloat162*>(smem + OFF_PH + r0 * ARS + colc * 2) =
                    __halves2bfloat162(h0a, h0b);
                *reinterpret_cast<__nv_bfloat162*>(smem + OFF_PL + r0 * ARS + colc * 2) =
                    __halves2bfloat162(__float2bfloat16(e0a - __bfloat162float(h0a)),
                                       __float2bfloat16(e0b - __bfloat162float(h0b)));
                *reinterpret_cast<__nv_bfloat162*>(smem + OFF_PH + (r0 + 8) * ARS + colc * 2) =
                    __halves2bfloat162(h1a, h1b);
                *reinterpret_cast<__nv_bfloat162*>(smem + OFF_PL + (r0 + 8) * ARS + colc * 2) =
                    __halves2bfloat162(__float2bfloat16(e1a - __bfloat162float(h1a)),
                                       __float2bfloat16(e1b - __bfloat162float(h1b)));
            }
            sum0 += __shfl_xor_sync(0xffffffffu, sum0, 1);
            sum0 += __shfl_xor_sync(0xffffffffu, sum0, 2);
            sum1 += __shfl_xor_sync(0xffffffffu, sum1, 1);
            sum1 += __shfl_xor_sync(0xffffffffu, sum1, 2);
            if ((lane & 3) == 0) {
                atomicAdd(&s_run[r0], sum0);
                atomicAdd(&s_run[r0 + 8], sum1);
            }
        }
        __syncthreads();

        #pragma unroll
        for (int ks = 0; ks < 4; ks++) {
            const int kk = ks * 16;
            uint32_t ph4[4], pl4[4], vh4[2][4], vl4[2][4];
            uint32_t aoff = (uint32_t)(arow * ARS + (kk + akd) * 2);
            ldm_x4(ph4, sbase + OFF_PH + aoff);
            ldm_x4(pl4, sbase + OFF_PL + aoff);
            #pragma unroll
            for (int g = 0; g < 2; g++) {
                uint32_t boff = (uint32_t)((wn + nrow8 + g * 16) * ARS + (kk + bkd) * 2);
                ldm_x4(vh4[g], sbase + OFF_VH + boff);
                ldm_x4(vl4[g], sbase + OFF_VL + boff);
            }
            #pragma unroll
            for (int nt = 0; nt < 4; nt++) {
                const uint32_t* b2h = &vh4[nt >> 1][(nt & 1) * 2];
                const uint32_t* b2l = &vl4[nt >> 1][(nt & 1) * 2];
                mma_bf16(acc2[nt], ph4, b2h);
                mma_bf16(acc2[nt], ph4, b2l);
                mma_bf16(acc2[nt], pl4, b2h);
            }
        }
    }
    __syncthreads();

    // epilogue: normalize, emit single fp16 for the out projection
    #pragma unroll
    for (int half = 0; half < 2; half++) {
        const int r  = r0 + half * 8;
        const float is = 1.0f / s_run[r];
        const size_t rowbase = (size_t)(b * Ssz + qs + r) * EMB + h * HD;
        #pragma unroll
        for (int nt = 0; nt < 4; nt++) {
            const int d = wn + nt * 8 + lc;
            float v0 = acc2[nt][half * 2 + 0] * is;
            float v1 = acc2[nt][half * 2 + 1] * is;
            *reinterpret_cast<__half2*>(g_av16 + rowbase + d) = __floats2half2_rn(v0, v1);
        }
    }
}

// ---------------------------------------------------------------------------
extern "C" void kernel_launch(void* const* d_in, const int* in_sizes, int n_in,
                              void* d_out, int out_size)
{
    const float* x    = (const float*)d_in[0];
    const int*   pm   = (const int*)  d_in[1];
    const float* Wqkv = (const float*)d_in[2];
    const float* bqkv = (const float*)d_in[3];
    const float* Wo   = (const float*)d_in[4];
    const float* bo   = (const float*)d_in[5];
    float* out = (float*)d_out;

    cudaFuncSetAttribute(attn_kernel,
                         cudaFuncAttributeMaxDynamicSharedMemorySize, ATTN_SMEM);
    cudaFuncSetAttribute(qkv_mma,
                         cudaFuncAttributeMaxDynamicSharedMemorySize, GEMM_SMEM);
    cudaFuncSetAttribute(out_mma,
                         cudaFuncAttributeMaxDynamicSharedMemorySize, GEMM_SMEM);

    conv_x16 <<<(M1*INDIM/4 + 255)/256, 256>>>((const float4*)x);
    conv_w16 <<<(N1*INDIM/4 + 255)/256, 256>>>((const float4*)Wqkv);
    conv_wo16<<<(EMB*EMB/4  + 255)/256, 256>>>((const float4*)Wo);

    qkv_mma<<<dim3(N1/128, M1/128), 256, GEMM_SMEM>>>(bqkv, pm);

    attn_kernel<<<dim3(Ssz/64, Bsz*NH), 256, ATTN_SMEM>>>();

    out_mma<<<dim3(EMB/128, M1/128), 256, GEMM_SMEM>>>(bo, out);
}

// round 13
// speedup vs baseline: 2.3607x; 1.2251x over previous
#include <cuda_runtime.h>
#include <cuda_fp16.h>
#include <math.h>
#include <cstdint>

#define Bsz   2
#define Ssz   2048
#define INDIM 1024
#define EMB   1024
#define NH    16
#define HD    64
#define PADW  128

#define M1 (Bsz*Ssz)   /* 4096 */
#define N1 (3*EMB)     /* 3072 */

// ---------------------------------------------------------------------------
// Baseline-ISA PTX helpers (compute_103-legal)
// ---------------------------------------------------------------------------
__device__ __forceinline__ uint32_t smem_to_u32(const void* p) {
    uint32_t a;
    asm("{ .reg .u64 t; cvta.to.shared.u64 t, %1; cvt.u32.u64 %0, t; }" : "=r"(a) : "l"(p));
    return a;
}
#define CP_ASYNC16(saddr, gptr) \
    asm volatile("cp.async.cg.shared.global [%0], [%1], 16;" :: "r"(saddr), "l"(gptr))
#define CP_COMMIT() asm volatile("cp.async.commit_group;" ::: "memory")
#define CP_WAIT1()  asm volatile("cp.async.wait_group 1;" ::: "memory")
#define CP_WAIT0()  asm volatile("cp.async.wait_group 0;" ::: "memory")

__device__ __forceinline__ void ldm_x4(uint32_t* r, uint32_t addr) {
    asm volatile("ldmatrix.sync.aligned.m8n8.x4.shared.b16 {%0,%1,%2,%3}, [%4];"
        : "=r"(r[0]), "=r"(r[1]), "=r"(r[2]), "=r"(r[3]) : "r"(addr));
}
__device__ __forceinline__ void mma_fp16(float* d, const uint32_t* a, const uint32_t* b) {
    asm volatile("mma.sync.aligned.m16n8k16.row.col.f32.f16.f16.f32 "
        "{%0,%1,%2,%3}, {%4,%5,%6,%7}, {%8,%9}, {%0,%1,%2,%3};"
        : "+f"(d[0]), "+f"(d[1]), "+f"(d[2]), "+f"(d[3])
        : "r"(a[0]), "r"(a[1]), "r"(a[2]), "r"(a[3]), "r"(b[0]), "r"(b[1]));
}

// ---------------------------------------------------------------------------
// Scratch (static device globals) — all fp16 now
// ---------------------------------------------------------------------------
__device__ __half g_x16[M1*INDIM];
__device__ __half g_w16[N1*INDIM];
__device__ __half g_wo16[EMB*EMB];
__device__ __half g_av16[M1*EMB];
__device__ __half g_q16[Bsz*NH*Ssz*HD];
__device__ __half g_k16[Bsz*NH*Ssz*HD];
__device__ __half g_vt16[Bsz*NH*HD*Ssz];   // V transposed [b,h,d,s]

// ---------------------------------------------------------------------------
// Single fused fp32 -> fp16 conversion kernel (x | Wqkv | Wo)
// ---------------------------------------------------------------------------
#define NX  ((M1*INDIM)/4)
#define NW  ((N1*INDIM)/4)
#define NWO ((EMB*EMB)/4)

__global__ void conv_all(const float4* __restrict__ x,
                         const float4* __restrict__ w,
                         const float4* __restrict__ wo)
{
    int i = blockIdx.x * blockDim.x + threadIdx.x;
    const float4* src;
    __half2* dst;
    int j;
    if (i < NX)            { src = x;  dst = (__half2*)g_x16;  j = i; }
    else if (i < NX + NW)  { src = w;  dst = (__half2*)g_w16;  j = i - NX; }
    else if (i < NX + NW + NWO) { src = wo; dst = (__half2*)g_wo16; j = i - NX - NW; }
    else return;
    float4 f = src[j];
    dst[2*j]   = __floats2half2_rn(f.x, f.y);
    dst[2*j+1] = __floats2half2_rn(f.z, f.w);
}

// ---------------------------------------------------------------------------
// Single-fp16 HMMA GEMM (validated round 12): CTA 128x128, BK=32, 8 warps,
// 3-stage cp.async pipeline, one __syncthreads per chunk. 61440 B smem.
// ---------------------------------------------------------------------------
#define TILE_B 10240
#define STG_SZ (2 * TILE_B)
#define GEMM_SMEM (3 * STG_SZ)

__device__ __forceinline__ void load2_async(
    const __half* a, const __half* bw,
    int m0, int n0, int k0, uint32_t sb, int stg, int t)
{
    uint32_t base = sb + stg * STG_SZ;
    #pragma unroll
    for (int i = 0; i < 2; i++) {
        int c  = t + i * 256;
        int r  = c >> 2;
        int kc = c & 3;
        size_t goffA = (size_t)(m0 + r) * 1024 + k0 + kc * 8;
        size_t goffB = (size_t)(n0 + r) * 1024 + k0 + kc * 8;
        uint32_t soff = (uint32_t)(r * 80 + kc * 16);
        CP_ASYNC16(base + soff,          a  + goffA);
        CP_ASYNC16(base + TILE_B + soff, bw + goffB);
    }
}

__device__ __forceinline__ void gemm1_mainloop(
    const __half* __restrict__ a, const __half* __restrict__ bw,
    int m0, int n0, uint32_t sb, int t, float acc[4][4][4])
{
    const int lane = t & 31, wid = t >> 5;
    const int wm = (wid >> 2) * 64, wn = (wid & 3) * 32;

    #pragma unroll
    for (int x = 0; x < 4; x++)
        #pragma unroll
        for (int y = 0; y < 4; y++)
            #pragma unroll
            for (int e = 0; e < 4; e++)
                acc[x][y][e] = 0.f;

    load2_async(a, bw, m0, n0, 0,  sb, 0, t); CP_COMMIT();
    load2_async(a, bw, m0, n0, 32, sb, 1, t); CP_COMMIT();

    const int arow = wm + (lane & 15);
    const int akd  = (lane & 16) >> 1;
    const int nrow = wn + (lane & 7) + ((lane & 16) >> 1);
    const int bkd  = (lane & 8);

    for (int ch = 0; ch < 32; ch++) {
        if (ch < 31) CP_WAIT1(); else CP_WAIT0();
        __syncthreads();
        if (ch + 2 < 32) {
            load2_async(a, bw, m0, n0, (ch + 2) * 32, sb, (ch + 2) % 3, t);
            CP_COMMIT();
        }
        const uint32_t base = sb + (ch % 3) * STG_SZ;
        #pragma unroll
        for (int ks = 0; ks < 2; ks++) {
            const int kk = ks * 16;
            uint32_t af[4][4], bwf[2][4];
            #pragma unroll
            for (int mt = 0; mt < 4; mt++) {
                uint32_t off = (uint32_t)((arow + mt * 16) * 80 + (kk + akd) * 2);
                ldm_x4(af[mt], base + off);
            }
            #pragma unroll
            for (int g = 0; g < 2; g++) {
                uint32_t off = (uint32_t)((nrow + g * 16) * 80 + (kk + bkd) * 2);
                ldm_x4(bwf[g], base + TILE_B + off);
            }
            #pragma unroll
            for (int mt = 0; mt < 4; mt++)
                #pragma unroll
                for (int nt = 0; nt < 4; nt++) {
                    const uint32_t* b2 = &bwf[nt >> 1][(nt & 1) * 2];
                    mma_fp16(acc[mt][nt], af[mt], b2);
                }
        }
    }
}

// QKV projection: bias + padding mask, emit single fp16 q,k [b,h,s,d],
// v transposed [b,h,d,s].
__global__ __launch_bounds__(256) void qkv_mma(
    const float* __restrict__ bias, const int* __restrict__ pm)
{
    extern __shared__ __align__(16) char smem[];
    const uint32_t sb = smem_to_u32(smem);
    const int t = threadIdx.x, lane = t & 31, wid = t >> 5;
    const int wm = (wid >> 2) * 64, wn = (wid & 3) * 32;
    const int n0 = blockIdx.x * 128, m0 = blockIdx.y * 128;

    float acc[4][4][4];
    gemm1_mainloop(g_x16, g_w16, m0, n0, sb, t, acc);

    const int lr = lane >> 2, lc = (lane & 3) * 2;
    #pragma unroll
    for (int mt = 0; mt < 4; mt++) {
        #pragma unroll
        for (int half = 0; half < 2; half++) {
            const int m = m0 + wm + mt * 16 + lr + half * 8;
            const int msk = pm[m];
            const int bb = m >> 11, s = m & 2047;
            #pragma unroll
            for (int nt = 0; nt < 4; nt++) {
                #pragma unroll
                for (int e = 0; e < 2; e++) {
                    const int n = n0 + wn + nt * 8 + lc + e;
                    float val = msk ? 0.0f : (acc[mt][nt][half * 2 + e] + bias[n]);
                    __half v16 = __float2half_rn(val);
                    int h  = n / 192;
                    int cc = n - h * 192;
                    if (cc < HD)
                        g_q16[((bb * NH + h) * Ssz + s) * HD + cc] = v16;
                    else if (cc < 2*HD)
                        g_k16[((bb * NH + h) * Ssz + s) * HD + cc - HD] = v16;
                    else
                        g_vt16[((bb * NH + h) * HD + cc - 2*HD) * Ssz + s] = v16;
                }
            }
        }
    }
}

// Output projection: out = attn_vals @ Wo^T + bo
__global__ __launch_bounds__(256) void out_mma(
    const float* __restrict__ bias, float* __restrict__ C)
{
    extern __shared__ __align__(16) char smem[];
    const uint32_t sb = smem_to_u32(smem);
    const int t = threadIdx.x, lane = t & 31, wid = t >> 5;
    const int wm = (wid >> 2) * 64, wn = (wid & 3) * 32;
    const int n0 = blockIdx.x * 128, m0 = blockIdx.y * 128;

    float acc[4][4][4];
    gemm1_mainloop(g_av16, g_wo16, m0, n0, sb, t, acc);

    const int lr = lane >> 2, lc = (lane & 3) * 2;
    #pragma unroll
    for (int mt = 0; mt < 4; mt++) {
        #pragma unroll
        for (int half = 0; half < 2; half++) {
            const int m = m0 + wm + mt * 16 + lr + half * 8;
            #pragma unroll
            for (int nt = 0; nt < 4; nt++) {
                const int n = n0 + wn + nt * 8 + lc;
                float2 o;
                o.x = acc[mt][nt][half * 2 + 0] + bias[n];
                o.y = acc[mt][nt][half * 2 + 1] + bias[n + 1];
                *reinterpret_cast<float2*>(C + (size_t)m * EMB + n) = o;
            }
        }
    }
}

// ---------------------------------------------------------------------------
// Banded attention, online softmax, SINGLE-fp16 QK and PV.
// One block per (b,h,64-query tile), 256 threads, ~38 KB smem, 2 CTAs/SM.
// ---------------------------------------------------------------------------
#define ARS  144
#define OFF_Q   0
#define OFF_K   9216
#define OFF_V   18432
#define OFF_P   27648
#define OFF_MR  36864
#define OFF_SR  (OFF_MR + 256)
#define OFF_ALP (OFF_MR + 512)
#define OFF_ST  (OFF_MR + 768)
#define ATTN_SMEM (OFF_MR + 768 + 512)   /* 38144 */

__global__ __launch_bounds__(256, 2) void attn_kernel()
{
    extern __shared__ __align__(16) char smem[];
    const uint32_t sbase = smem_to_u32(smem);
    float* m_run = (float*)(smem + OFF_MR);
    float* s_run = (float*)(smem + OFF_SR);
    float* alphv = (float*)(smem + OFF_ALP);
    float* stats = (float*)(smem + OFF_ST);

    const int t = threadIdx.x, lane = t & 31, w = t >> 5;
    const int b  = blockIdx.y >> 4, h = blockIdx.y & 15;
    const int qs = blockIdx.x * 64;
    const int kb = qs - PADW;

    const size_t qkbase = (size_t)(b * NH + h) * Ssz * HD;
    const size_t vbase  = (size_t)(b * NH + h) * HD * Ssz;

    const int wm4 = (w >> 1) << 4;
    const int wnI = w & 1;
    const int wn  = wnI << 5;
    const int arow = wm4 + (lane & 15);
    const int akd  = (lane & 16) >> 1;
    const int nrow8 = (lane & 7) + ((lane & 16) >> 1);
    const int bkd  = (lane & 8);
    const int lr = lane >> 2, lc = (lane & 3) * 2;
    const int r0 = wm4 + lr;
    const float scale = 0.125f;

    if (t < 64) { m_run[t] = -1e30f; s_run[t] = 0.f; }
    // load Q tile (64x64 fp16)
    #pragma unroll
    for (int i = 0; i < 2; i++) {
        int u = t + i * 256;
        int row = u >> 3;
        int c8  = (u & 7) * 8;
        *reinterpret_cast<uint4*>(smem + OFF_Q + row * ARS + c8 * 2) =
            *reinterpret_cast<const uint4*>(g_q16 + qkbase + (size_t)(qs + row) * HD + c8);
    }

    float acc2[4][4];
    #pragma unroll
    for (int nt = 0; nt < 4; nt++)
        #pragma unroll
        for (int e = 0; e < 4; e++) acc2[nt][e] = 0.f;

    for (int ch = 0; ch < 5; ch++) {
        __syncthreads();
        // load K chunk [key 64][d 64] and V^T chunk [d 64][key 64]
        #pragma unroll
        for (int i = 0; i < 2; i++) {
            int u   = t + i * 256;
            int row = u >> 3;
            int c8  = (u & 7) * 8;
            uint32_t soff = (uint32_t)(row * ARS + c8 * 2);
            int j = kb + ch * 64 + row;
            uint4 kk4 = make_uint4(0,0,0,0);
            if (j >= 0 && j < Ssz)
                kk4 = *reinterpret_cast<const uint4*>(g_k16 + qkbase + (size_t)j * HD + c8);
            *reinterpret_cast<uint4*>(smem + OFF_K + soff) = kk4;
            int j0 = kb + ch * 64 + c8;
            uint4 vv4 = make_uint4(0,0,0,0);
            if (j0 >= 0 && j0 < Ssz)
                vv4 = *reinterpret_cast<const uint4*>(g_vt16 + vbase + (size_t)row * Ssz + j0);
            *reinterpret_cast<uint4*>(smem + OFF_V + soff) = vv4;
        }
        __syncthreads();

        // S = Q K^T (single fp16 HMMA)
        float s[4][4];
        #pragma unroll
        for (int nt = 0; nt < 4; nt++)
            #pragma unroll
            for (int e = 0; e < 4; e++) s[nt][e] = 0.f;

        #pragma unroll
        for (int ks = 0; ks < 4; ks++) {
            const int kk = ks * 16;
            uint32_t q4[4], k4[2][4];
            ldm_x4(q4, sbase + OFF_Q + (uint32_t)(arow * ARS + (kk + akd) * 2));
            #pragma unroll
            for (int g = 0; g < 2; g++)
                ldm_x4(k4[g], sbase + OFF_K +
                       (uint32_t)((wn + nrow8 + g * 16) * ARS + (kk + bkd) * 2));
            #pragma unroll
            for (int nt = 0; nt < 4; nt++)
                mma_fp16(s[nt], q4, &k4[nt >> 1][(nt & 1) * 2]);
        }

        // mask + per-row chunk max
        float mx0 = -1e30f, mx1 = -1e30f;
        #pragma unroll
        for (int nt = 0; nt < 4; nt++) {
            #pragma unroll
            for (int e = 0; e < 2; e++) {
                const int C = ch * 64 + wn + nt * 8 + lc + e;
                const int j = kb + C;
                const bool jv = (j >= 0) && (j < Ssz);
                if (!(jv && C >= r0 && C <= r0 + 256))          s[nt][e]     = -1e30f;
                if (!(jv && C >= r0 + 8 && C <= r0 + 8 + 256))  s[nt][2 + e] = -1e30f;
                mx0 = fmaxf(mx0, s[nt][e]);
                mx1 = fmaxf(mx1, s[nt][2 + e]);
            }
        }
        mx0 = fmaxf(mx0, __shfl_xor_sync(0xffffffffu, mx0, 1));
        mx0 = fmaxf(mx0, __shfl_xor_sync(0xffffffffu, mx0, 2));
        mx1 = fmaxf(mx1, __shfl_xor_sync(0xffffffffu, mx1, 1));
        mx1 = fmaxf(mx1, __shfl_xor_sync(0xffffffffu, mx1, 2));
        if ((lane & 3) == 0) {
            stats[r0 * 2 + wnI]       = mx0;
            stats[(r0 + 8) * 2 + wnI] = mx1;
        }
        __syncthreads();

        if (t < 64) {
            float mc = fmaxf(stats[t * 2], stats[t * 2 + 1]);
            float mo = m_run[t];
            float mn = fmaxf(mo, mc);
            float a  = __expf((mo - mn) * scale);
            alphv[t] = a;
            m_run[t] = mn;
            s_run[t] *= a;
        }
        __syncthreads();

        // rescale acc2, P = exp((s-m)*scale) -> fp16, row sums
        {
            const float a0 = alphv[r0], a1 = alphv[r0 + 8];
            #pragma unroll
            for (int nt = 0; nt < 4; nt++) {
                acc2[nt][0] *= a0; acc2[nt][1] *= a0;
                acc2[nt][2] *= a1; acc2[nt][3] *= a1;
            }
            const float mn0 = m_run[r0] * scale, mn1 = m_run[r0 + 8] * scale;
            float sum0 = 0.f, sum1 = 0.f;
            #pragma unroll
            for (int nt = 0; nt < 4; nt++) {
                const int colc = wn + nt * 8 + lc;
                float e0a = __expf(s[nt][0] * scale - mn0);
                float e0b = __expf(s[nt][1] * scale - mn0);
                float e1a = __expf(s[nt][2] * scale - mn1);
                float e1b = __expf(s[nt][3] * scale - mn1);
                sum0 += e0a + e0b;
                sum1 += e1a + e1b;
                *reinterpret_cast<__half2*>(smem + OFF_P + r0 * ARS + colc * 2) =
                    __floats2half2_rn(e0a, e0b);
                *reinterpret_cast<__half2*>(smem + OFF_P + (r0 + 8) * ARS + colc * 2) =
                    __floats2half2_rn(e1a, e1b);
            }
            sum0 += __shfl_xor_sync(0xffffffffu, sum0, 1);
            sum0 += __shfl_xor_sync(0xffffffffu, sum0, 2);
            sum1 += __shfl_xor_sync(0xffffffffu, sum1, 1);
            sum1 += __shfl_xor_sync(0xffffffffu, sum1, 2);
            if ((lane & 3) == 0) {
                atomicAdd(&s_run[r0], sum0);
                atomicAdd(&s_run[r0 + 8], sum1);
            }
        }
        __syncthreads();

        // PV: acc2 += P_chunk @ V_chunk (single fp16 HMMA)
        #pragma unroll
        for (int ks = 0; ks < 4; ks++) {
            const int kk = ks * 16;
            uint32_t p4[4], v4[2][4];
            ldm_x4(p4, sbase + OFF_P + (uint32_t)(arow * ARS + (kk + akd) * 2));
            #pragma unroll
            for (int g = 0; g < 2; g++)
                ldm_x4(v4[g], sbase + OFF_V +
                       (uint32_t)((wn + nrow8 + g * 16) * ARS + (kk + bkd) * 2));
            #pragma unroll
            for (int nt = 0; nt < 4; nt++)
                mma_fp16(acc2[nt], p4, &v4[nt >> 1][(nt & 1) * 2]);
        }
    }
    __syncthreads();

    // epilogue: normalize, emit single fp16 for the out projection
    #pragma unroll
    for (int half = 0; half < 2; half++) {
        const int r  = r0 + half * 8;
        const float is = 1.0f / s_run[r];
        const size_t rowbase = (size_t)(b * Ssz + qs + r) * EMB + h * HD;
        #pragma unroll
        for (int nt = 0; nt < 4; nt++) {
            const int d = wn + nt * 8 + lc;
            float v0 = acc2[nt][half * 2 + 0] * is;
            float v1 = acc2[nt][half * 2 + 1] * is;
            *reinterpret_cast<__half2*>(g_av16 + rowbase + d) = __floats2half2_rn(v0, v1);
        }
    }
}

// ---------------------------------------------------------------------------
extern "C" void kernel_launch(void* const* d_in, const int* in_sizes, int n_in,
                              void* d_out, int out_size)
{
    const float* x    = (const float*)d_in[0];
    const int*   pm   = (const int*)  d_in[1];
    const float* Wqkv = (const float*)d_in[2];
    const float* bqkv = (const float*)d_in[3];
    const float* Wo   = (const float*)d_in[4];
    const float* bo   = (const float*)d_in[5];
    float* out = (float*)d_out;

    cudaFuncSetAttribute(attn_kernel,
                         cudaFuncAttributeMaxDynamicSharedMemorySize, ATTN_SMEM);
    cudaFuncSetAttribute(qkv_mma,
                         cudaFuncAttributeMaxDynamicSharedMemorySize, GEMM_SMEM);
    cudaFuncSetAttribute(out_mma,
                         cudaFuncAttributeMaxDynamicSharedMemorySize, GEMM_SMEM);

    conv_all<<<(NX + NW + NWO + 255)/256, 256>>>(
        (const float4*)x, (const float4*)Wqkv, (const float4*)Wo);

    qkv_mma<<<dim3(N1/128, M1/128), 256, GEMM_SMEM>>>(bqkv, pm);

    attn_kernel<<<dim3(Ssz/64, Bsz*NH), 256, ATTN_SMEM>>>();

    out_mma<<<dim3(EMB/128, M1/128), 256, GEMM_SMEM>>>(bo, out);
}